// round 2
// baseline (speedup 1.0000x reference)
#include <cuda_runtime.h>
#include <cuda_bf16.h>
#include <cstddef>

// ---------------------------------------------------------------------------
// Problem constants
// ---------------------------------------------------------------------------
#define BSZ   4
#define SEQ   2048
#define DM    1024
#define NH    16
#define DK    64
#define DFF   4096
#define NTOK  (BSZ*SEQ)            // 8192

// ---------------------------------------------------------------------------
// Scratch (device globals: allocation-free per harness rules)
// ---------------------------------------------------------------------------
__device__ float g_h   [(size_t)NTOK*DM];   // ln output (reused for ln2)
__device__ float g_q   [(size_t)NTOK*DM];
__device__ float g_k   [(size_t)NTOK*DM];
__device__ float g_v   [(size_t)NTOK*DM];
__device__ float g_attn[(size_t)NTOK*DM];
__device__ float g_x2  [(size_t)NTOK*DM];
__device__ float g_ff  [(size_t)NTOK*DFF];

// ---------------------------------------------------------------------------
// Packed f32x2 helpers (Blackwell FFMA2 path — ptxas won't auto-fuse)
// ---------------------------------------------------------------------------
__device__ __forceinline__ unsigned long long pack2(float lo, float hi) {
    unsigned long long r;
    asm("mov.b64 %0, {%1, %2};" : "=l"(r) : "f"(lo), "f"(hi));
    return r;
}
__device__ __forceinline__ float2 unpack2(unsigned long long v) {
    float2 r;
    asm("mov.b64 {%0, %1}, %2;" : "=f"(r.x), "=f"(r.y) : "l"(v));
    return r;
}
__device__ __forceinline__ unsigned long long fma2(unsigned long long a,
                                                   unsigned long long b,
                                                   unsigned long long c) {
    unsigned long long d;
    asm("fma.rn.f32x2 %0, %1, %2, %3;" : "=l"(d) : "l"(a), "l"(b), "l"(c));
    return d;
}
__device__ __forceinline__ unsigned long long mul2(unsigned long long a,
                                                   unsigned long long b) {
    unsigned long long d;
    asm("mul.rn.f32x2 %0, %1, %2;" : "=l"(d) : "l"(a), "l"(b));
    return d;
}

__device__ __forceinline__ float gelu_exact(float v) {
    return 0.5f * v * (1.0f + erff(v * 0.70710678118654752440f));
}

// ---------------------------------------------------------------------------
// LayerNorm: one block (256 thr) per token, D=1024 -> 1 float4 per thread
// ---------------------------------------------------------------------------
__global__ __launch_bounds__(256)
void ln_kernel(const float* __restrict__ x, const float* __restrict__ g,
               const float* __restrict__ b, float* __restrict__ y)
{
    const int t = blockIdx.x;
    const int i = threadIdx.x;
    const float* xp = x + (size_t)t * DM;

    float4 v = *(const float4*)(xp + i * 4);
    float s  = (v.x + v.y) + (v.z + v.w);
    float ss = fmaf(v.x, v.x, fmaf(v.y, v.y, fmaf(v.z, v.z, v.w * v.w)));

    #pragma unroll
    for (int o = 16; o > 0; o >>= 1) {
        s  += __shfl_xor_sync(0xFFFFFFFFu, s,  o);
        ss += __shfl_xor_sync(0xFFFFFFFFu, ss, o);
    }
    __shared__ float sh[16];
    const int w = i >> 5;
    if ((i & 31) == 0) { sh[w] = s; sh[8 + w] = ss; }
    __syncthreads();
    float S = 0.f, SS = 0.f;
    #pragma unroll
    for (int k = 0; k < 8; k++) { S += sh[k]; SS += sh[8 + k]; }

    const float mean = S * (1.0f / DM);
    const float var  = SS * (1.0f / DM) - mean * mean;
    const float r    = rsqrtf(var + 1e-5f);

    float4 gg = *(const float4*)(g + i * 4);
    float4 bb = *(const float4*)(b + i * 4);
    float4 o;
    o.x = (v.x - mean) * r * gg.x + bb.x;
    o.y = (v.y - mean) * r * gg.y + bb.y;
    o.z = (v.z - mean) * r * gg.z + bb.z;
    o.w = (v.w - mean) * r * gg.w + bb.w;
    *(float4*)(y + (size_t)t * DM + i * 4) = o;
}

// ---------------------------------------------------------------------------
// Tiled SGEMM with packed f32x2 FMA. C[M,N] = A[M,K]@B[K,N] + bias (+epilogue)
// BM=128, BN=128, BK=16, 256 threads, 8x8 per-thread microtile.
// ---------------------------------------------------------------------------
#define EPI_BIAS  0
#define EPI_RESID 1
#define EPI_GELU  2

#define GBM 128
#define GBN 128
#define GBK 16

template<int EPI>
__global__ __launch_bounds__(256)
void gemm_kernel(const float* __restrict__ A, const float* __restrict__ B,
                 const float* __restrict__ bias, const float* __restrict__ res,
                 float* __restrict__ C, int M, int N, int K)
{
    __shared__ __align__(16) float As[GBK][GBM];
    __shared__ __align__(16) float Bs[GBK][GBN];

    const int tid = threadIdx.x;
    const int tx  = tid & 15;          // 0..15  -> 8 cols each
    const int ty  = tid >> 4;          // 0..15  -> 8 rows each
    const int row0 = blockIdx.y * GBM;
    const int col0 = blockIdx.x * GBN;

    unsigned long long acc[8][4];
    #pragma unroll
    for (int i = 0; i < 8; i++)
        #pragma unroll
        for (int j = 0; j < 4; j++) acc[i][j] = 0ull;

    for (int k0 = 0; k0 < K; k0 += GBK) {
        // load A tile (128 x 16), store transposed As[k][m]
        #pragma unroll
        for (int l = 0; l < 2; l++) {
            int f  = tid + l * 256;              // 0..511 float4s
            int r  = f >> 2;                     // 0..127
            int kq = (f & 3) << 2;               // 0,4,8,12
            float4 v = *(const float4*)(A + (size_t)(row0 + r) * K + k0 + kq);
            As[kq + 0][r] = v.x;
            As[kq + 1][r] = v.y;
            As[kq + 2][r] = v.z;
            As[kq + 3][r] = v.w;
        }
        // load B tile (16 x 128), natural layout
        #pragma unroll
        for (int l = 0; l < 2; l++) {
            int f  = tid + l * 256;
            int kr = f >> 5;                     // 0..15
            int cq = (f & 31) << 2;              // 0..124
            *(float4*)&Bs[kr][cq] =
                *(const float4*)(B + (size_t)(k0 + kr) * N + col0 + cq);
        }
        __syncthreads();

        #pragma unroll
        for (int k = 0; k < GBK; k++) {
            float4 aA = *(const float4*)&As[k][ty * 8];
            float4 aB = *(const float4*)&As[k][ty * 8 + 4];
            ulonglong2 b01 = *(const ulonglong2*)&Bs[k][tx * 8];
            ulonglong2 b23 = *(const ulonglong2*)&Bs[k][tx * 8 + 4];
            unsigned long long av[8];
            av[0] = pack2(aA.x, aA.x); av[1] = pack2(aA.y, aA.y);
            av[2] = pack2(aA.z, aA.z); av[3] = pack2(aA.w, aA.w);
            av[4] = pack2(aB.x, aB.x); av[5] = pack2(aB.y, aB.y);
            av[6] = pack2(aB.z, aB.z); av[7] = pack2(aB.w, aB.w);
            unsigned long long bv[4] = { b01.x, b01.y, b23.x, b23.y };
            #pragma unroll
            for (int i = 0; i < 8; i++)
                #pragma unroll
                for (int j = 0; j < 4; j++)
                    acc[i][j] = fma2(av[i], bv[j], acc[i][j]);
        }
        __syncthreads();
    }

    // epilogue
    #pragma unroll
    for (int i = 0; i < 8; i++) {
        const int r = row0 + ty * 8 + i;
        float*       crow = C   + (size_t)r * N;
        const float* rrow = (EPI == EPI_RESID) ? (res + (size_t)r * N) : nullptr;
        #pragma unroll
        for (int j = 0; j < 4; j++) {
            const int c = col0 + tx * 8 + j * 2;
            float2 v = unpack2(acc[i][j]);
            v.x += bias[c];
            v.y += bias[c + 1];
            if (EPI == EPI_GELU) {
                v.x = gelu_exact(v.x);
                v.y = gelu_exact(v.y);
            }
            if (EPI == EPI_RESID) {
                v.x += rrow[c];
                v.y += rrow[c + 1];
            }
            *(float2*)&crow[c] = v;
        }
    }
}

// ---------------------------------------------------------------------------
// Flash attention (fp32). Q/K/V stored token-major [B,S,D]; head h occupies
// columns [h*64, h*64+64). One thread = one query row. Bc=32 keys per tile.
// ---------------------------------------------------------------------------
#define FA_BR 128
#define FA_BC 32

__global__ __launch_bounds__(128)
void flash_attn_kernel(const float* __restrict__ Q, const float* __restrict__ K,
                       const float* __restrict__ V, const int* __restrict__ mask,
                       float* __restrict__ O)
{
    const int bh = blockIdx.x;           // 0..63
    const int b  = bh >> 4;
    const int h  = bh & 15;
    const int tid = threadIdx.x;
    const int qi  = blockIdx.y * FA_BR + tid;   // query index within sequence

    const float* qptr  = Q + ((size_t)(b * SEQ + qi)) * DM + h * DK;
    const float* kbase = K + ((size_t)(b * SEQ)) * DM + h * DK;
    const float* vbase = V + ((size_t)(b * SEQ)) * DM + h * DK;

    // q pre-scaled by 1/sqrt(Dk), packed as 32 f32x2
    unsigned long long q2[32], o2[32];
    #pragma unroll
    for (int d4 = 0; d4 < 16; d4++) {
        float4 v = *(const float4*)(qptr + 4 * d4);
        q2[2 * d4 + 0] = pack2(v.x * 0.125f, v.y * 0.125f);
        q2[2 * d4 + 1] = pack2(v.z * 0.125f, v.w * 0.125f);
        o2[2 * d4 + 0] = 0ull;
        o2[2 * d4 + 1] = 0ull;
    }

    float m = -1e30f, l = 0.f;

    __shared__ __align__(16) float Ks[FA_BC][DK];
    __shared__ __align__(16) float Vs[FA_BC][DK];
    __shared__ int ms[FA_BC];

    for (int kc = 0; kc < SEQ; kc += FA_BC) {
        __syncthreads();
        // cooperative tile load: 2 tiles x 512 float4 over 128 threads
        #pragma unroll
        for (int lu = 0; lu < 4; lu++) {
            int f  = tid + lu * 128;          // 0..511
            int r  = f >> 4;                  // 0..31
            int c4 = (f & 15) << 2;           // 0..60
            *(float4*)&Ks[r][c4] = *(const float4*)(kbase + (size_t)(kc + r) * DM + c4);
            *(float4*)&Vs[r][c4] = *(const float4*)(vbase + (size_t)(kc + r) * DM + c4);
        }
        if (tid < FA_BC) ms[tid] = mask[b * SEQ + kc + tid];
        __syncthreads();

        // scores for this tile
        float s[FA_BC];
        float tmax = -1e30f;
        #pragma unroll
        for (int j = 0; j < FA_BC; j++) {
            const ulonglong2* kj = (const ulonglong2*)&Ks[j][0];
            unsigned long long a0 = 0ull, a1 = 0ull, a2 = 0ull, a3 = 0ull;
            #pragma unroll
            for (int d4 = 0; d4 < 16; d4 += 2) {
                ulonglong2 k0 = kj[d4];
                ulonglong2 k1 = kj[d4 + 1];
                a0 = fma2(q2[2 * d4 + 0], k0.x, a0);
                a1 = fma2(q2[2 * d4 + 1], k0.y, a1);
                a2 = fma2(q2[2 * d4 + 2], k1.x, a2);
                a3 = fma2(q2[2 * d4 + 3], k1.y, a3);
            }
            float2 f0 = unpack2(a0), f1 = unpack2(a1);
            float2 f2 = unpack2(a2), f3 = unpack2(a3);
            float sc = ((f0.x + f0.y) + (f1.x + f1.y))
                     + ((f2.x + f2.y) + (f3.x + f3.y));
            if (ms[j] == 0) sc = -1e9f;
            s[j] = sc;
            tmax = fmaxf(tmax, sc);
        }

        // online softmax (tile-level rescale)
        const float m_new = fmaxf(m, tmax);
        const float corr  = __expf(m - m_new);
        l *= corr;
        const unsigned long long c2 = pack2(corr, corr);
        #pragma unroll
        for (int d = 0; d < 32; d++) o2[d] = mul2(o2[d], c2);

        #pragma unroll
        for (int j = 0; j < FA_BC; j++) {
            const float p = __expf(s[j] - m_new);
            l += p;
            const unsigned long long p2 = pack2(p, p);
            const ulonglong2* vj = (const ulonglong2*)&Vs[j][0];
            #pragma unroll
            for (int d4 = 0; d4 < 16; d4++) {
                ulonglong2 vv = vj[d4];
                o2[2 * d4 + 0] = fma2(p2, vv.x, o2[2 * d4 + 0]);
                o2[2 * d4 + 1] = fma2(p2, vv.y, o2[2 * d4 + 1]);
            }
        }
        m = m_new;
    }

    const float inv = 1.0f / l;
    float* optr = O + ((size_t)(b * SEQ + qi)) * DM + h * DK;
    #pragma unroll
    for (int d = 0; d < 32; d++) {
        float2 v = unpack2(o2[d]);
        v.x *= inv; v.y *= inv;
        *(float2*)&optr[2 * d] = v;
    }
}

// ---------------------------------------------------------------------------
// kernel_launch
// ---------------------------------------------------------------------------
extern "C" void kernel_launch(void* const* d_in, const int* in_sizes, int n_in,
                              void* d_out, int out_size)
{
    (void)in_sizes; (void)n_in; (void)out_size;
    const float* x     = (const float*)d_in[0];
    const int*   mask  = (const int*)  d_in[1];
    const float* Wq    = (const float*)d_in[2];
    const float* bq    = (const float*)d_in[3];
    const float* Wk    = (const float*)d_in[4];
    const float* bk    = (const float*)d_in[5];
    const float* Wv    = (const float*)d_in[6];
    const float* bv    = (const float*)d_in[7];
    const float* Wo    = (const float*)d_in[8];
    const float* bo    = (const float*)d_in[9];
    const float* W1    = (const float*)d_in[10];
    const float* b1    = (const float*)d_in[11];
    const float* W2    = (const float*)d_in[12];
    const float* b2    = (const float*)d_in[13];
    const float* ln1_g = (const float*)d_in[14];
    const float* ln1_b = (const float*)d_in[15];
    const float* ln2_g = (const float*)d_in[16];
    const float* ln2_b = (const float*)d_in[17];
    float* out = (float*)d_out;

    float *h, *q, *k, *v, *attn, *x2, *ff;
    cudaGetSymbolAddress((void**)&h,    g_h);
    cudaGetSymbolAddress((void**)&q,    g_q);
    cudaGetSymbolAddress((void**)&k,    g_k);
    cudaGetSymbolAddress((void**)&v,    g_v);
    cudaGetSymbolAddress((void**)&attn, g_attn);
    cudaGetSymbolAddress((void**)&x2,   g_x2);
    cudaGetSymbolAddress((void**)&ff,   g_ff);

    const dim3 gD (DM  / GBN, NTOK / GBM);   // (8, 64)
    const dim3 gFF(DFF / GBN, NTOK / GBM);   // (32, 64)

    // 1) h = LN1(x)
    ln_kernel<<<NTOK, 256>>>(x, ln1_g, ln1_b, h);
    // 2) Q,K,V projections (token-major layout)
    gemm_kernel<EPI_BIAS><<<gD, 256>>>(h, Wq, bq, nullptr, q, NTOK, DM, DM);
    gemm_kernel<EPI_BIAS><<<gD, 256>>>(h, Wk, bk, nullptr, k, NTOK, DM, DM);
    gemm_kernel<EPI_BIAS><<<gD, 256>>>(h, Wv, bv, nullptr, v, NTOK, DM, DM);
    // 3) attention
    flash_attn_kernel<<<dim3(BSZ * NH, SEQ / FA_BR), 128>>>(q, k, v, mask, attn);
    // 4) x2 = x + attn @ Wo + bo
    gemm_kernel<EPI_RESID><<<gD, 256>>>(attn, Wo, bo, x, x2, NTOK, DM, DM);
    // 5) h = LN2(x2)
    ln_kernel<<<NTOK, 256>>>(x2, ln2_g, ln2_b, h);
    // 6) ff = gelu(h @ W1 + b1)
    gemm_kernel<EPI_GELU><<<gFF, 256>>>(h, W1, b1, nullptr, ff, NTOK, DFF, DM);
    // 7) out = x2 + ff @ W2 + b2
    gemm_kernel<EPI_RESID><<<gD, 256>>>(ff, W2, b2, x2, out, NTOK, DM, DFF);
}

// round 6
// speedup vs baseline: 1.6406x; 1.6406x over previous
#include <cuda_runtime.h>
#include <cuda_bf16.h>
#include <cstddef>
#include <cstdint>

// ---------------------------------------------------------------------------
// Problem constants
// ---------------------------------------------------------------------------
#define BSZ   4
#define SEQ   2048
#define DM    1024
#define NH    16
#define DK    64
#define DFF   4096
#define NTOK  (BSZ*SEQ)            // 8192

// ---------------------------------------------------------------------------
// Scratch (device globals: allocation-free per harness rules)
// ---------------------------------------------------------------------------
__device__ float g_h   [(size_t)NTOK*DM];
__device__ float g_q   [(size_t)NTOK*DM];
__device__ float g_k   [(size_t)NTOK*DM];
__device__ float g_v   [(size_t)NTOK*DM];
__device__ float g_attn[(size_t)NTOK*DM];
__device__ float g_x2  [(size_t)NTOK*DM];
__device__ float g_ff  [(size_t)NTOK*DFF];
// transposed (tf32-rounded) weights: WT[n][k]
__device__ float g_wqT [(size_t)DM*DM];
__device__ float g_wkT [(size_t)DM*DM];
__device__ float g_wvT [(size_t)DM*DM];
__device__ float g_woT [(size_t)DM*DM];
__device__ float g_w1T [(size_t)DM*DFF];
__device__ float g_w2T [(size_t)DFF*DM];

// ---------------------------------------------------------------------------
// Helpers
// ---------------------------------------------------------------------------
__device__ __forceinline__ float to_tf32(float x) {
    float r;
    asm("cvt.rna.tf32.f32 %0, %1;" : "=f"(r) : "f"(x));
    return r;
}

__device__ __forceinline__ float gelu_exact(float v) {
    return 0.5f * v * (1.0f + erff(v * 0.70710678118654752440f));
}

// legacy tensor-core mma (sm_80+; compiles under plain sm_103 target)
__device__ __forceinline__ void mma_tf32(float& c0, float& c1, float& c2, float& c3,
                                         uint32_t a0, uint32_t a1, uint32_t a2, uint32_t a3,
                                         uint32_t b0, uint32_t b1) {
    asm volatile(
        "mma.sync.aligned.m16n8k8.row.col.f32.tf32.tf32.f32 "
        "{%0,%1,%2,%3}, {%4,%5,%6,%7}, {%8,%9}, {%0,%1,%2,%3};"
        : "+f"(c0), "+f"(c1), "+f"(c2), "+f"(c3)
        : "r"(a0), "r"(a1), "r"(a2), "r"(a3), "r"(b0), "r"(b1));
}

// packed f32x2 (for flash attention)
__device__ __forceinline__ unsigned long long pack2(float lo, float hi) {
    unsigned long long r;
    asm("mov.b64 %0, {%1, %2};" : "=l"(r) : "f"(lo), "f"(hi));
    return r;
}
__device__ __forceinline__ float2 unpack2(unsigned long long v) {
    float2 r;
    asm("mov.b64 {%0, %1}, %2;" : "=f"(r.x), "=f"(r.y) : "l"(v));
    return r;
}
__device__ __forceinline__ unsigned long long fma2(unsigned long long a,
                                                   unsigned long long b,
                                                   unsigned long long c) {
    unsigned long long d;
    asm("fma.rn.f32x2 %0, %1, %2, %3;" : "=l"(d) : "l"(a), "l"(b), "l"(c));
    return d;
}
__device__ __forceinline__ unsigned long long mul2(unsigned long long a,
                                                   unsigned long long b) {
    unsigned long long d;
    asm("mul.rn.f32x2 %0, %1, %2;" : "=l"(d) : "l"(a), "l"(b));
    return d;
}

// ---------------------------------------------------------------------------
// Weight transpose with tf32 rounding: W[K][N] -> WT[N][K]
// ---------------------------------------------------------------------------
__global__ __launch_bounds__(256)
void transpose_tf32(const float* __restrict__ W, float* __restrict__ WT, int K, int N)
{
    __shared__ float t[32][33];
    const int tx = threadIdx.x, ty = threadIdx.y;
    const int n0 = blockIdx.x * 32, k0 = blockIdx.y * 32;
    #pragma unroll
    for (int j = ty; j < 32; j += 8)
        t[j][tx] = to_tf32(W[(size_t)(k0 + j) * N + n0 + tx]);
    __syncthreads();
    #pragma unroll
    for (int j = ty; j < 32; j += 8)
        WT[(size_t)(n0 + j) * K + k0 + tx] = t[tx][j];
}

// ---------------------------------------------------------------------------
// LayerNorm: one block (256 thr) per token
// ---------------------------------------------------------------------------
__global__ __launch_bounds__(256)
void ln_kernel(const float* __restrict__ x, const float* __restrict__ g,
               const float* __restrict__ b, float* __restrict__ y)
{
    const int t = blockIdx.x;
    const int i = threadIdx.x;
    const float* xp = x + (size_t)t * DM;

    float4 v = *(const float4*)(xp + i * 4);
    float s  = (v.x + v.y) + (v.z + v.w);
    float ss = fmaf(v.x, v.x, fmaf(v.y, v.y, fmaf(v.z, v.z, v.w * v.w)));

    #pragma unroll
    for (int o = 16; o > 0; o >>= 1) {
        s  += __shfl_xor_sync(0xFFFFFFFFu, s,  o);
        ss += __shfl_xor_sync(0xFFFFFFFFu, ss, o);
    }
    __shared__ float sh[16];
    const int w = i >> 5;
    if ((i & 31) == 0) { sh[w] = s; sh[8 + w] = ss; }
    __syncthreads();
    float S = 0.f, SS = 0.f;
    #pragma unroll
    for (int k = 0; k < 8; k++) { S += sh[k]; SS += sh[8 + k]; }

    const float mean = S * (1.0f / DM);
    const float var  = SS * (1.0f / DM) - mean * mean;
    const float r    = rsqrtf(var + 1e-5f);

    float4 gg = *(const float4*)(g + i * 4);
    float4 bb = *(const float4*)(b + i * 4);
    float4 o;
    o.x = (v.x - mean) * r * gg.x + bb.x;
    o.y = (v.y - mean) * r * gg.y + bb.y;
    o.z = (v.z - mean) * r * gg.z + bb.z;
    o.w = (v.w - mean) * r * gg.w + bb.w;
    *(float4*)(y + (size_t)t * DM + i * 4) = o;
}

// ---------------------------------------------------------------------------
// TF32 mma.sync GEMM.  C[M,N] = A[M,K] @ BT[N,K]^T + bias (+epilogue)
// CTA tile 128x128, 8 warps (2x4), warp tile 64x32 (4x4 m16n8k8 frags).
// SMEM stride 20 floats -> conflict-free fragment loads.
// ---------------------------------------------------------------------------
#define EPI_BIAS  0
#define EPI_RESID 1
#define EPI_GELU  2

#define MBK   16
#define SSTR  20      // padded row stride in floats (conflict-free: 20*g mod 32 disjoint)

template<int EPI>
__global__ __launch_bounds__(256)
void mma_gemm(const float* __restrict__ A, const float* __restrict__ BT,
              const float* __restrict__ bias, const float* __restrict__ res,
              float* __restrict__ C, int M, int N, int K)
{
    __shared__ __align__(16) float As[2][128 * SSTR];
    __shared__ __align__(16) float Bs[2][128 * SSTR];

    const int tid  = threadIdx.x;
    const int wid  = tid >> 5;
    const int lane = tid & 31;
    const int g    = lane >> 2;       // group id (row within fragment)
    const int t    = lane & 3;        // thread-in-group (col within fragment)

    const int warp_m = (wid & 1) * 64;     // 2 warps down
    const int warp_n = (wid >> 1) * 32;    // 4 warps across
    const int row0 = blockIdx.y * 128;
    const int col0 = blockIdx.x * 128;

    float c[4][4][4];
    #pragma unroll
    for (int i = 0; i < 4; i++)
        #pragma unroll
        for (int j = 0; j < 4; j++)
            #pragma unroll
            for (int q = 0; q < 4; q++) c[i][j][q] = 0.f;

    // ---- tile loader: 512 float4 over 256 threads (2 each) per matrix ----
    auto load_tile = [&](int s, int kk) {
        #pragma unroll
        for (int i = 0; i < 2; i++) {
            const int f  = tid + i * 256;      // 0..511
            const int r  = f >> 2;             // 0..127
            const int c4 = (f & 3) * 4;        // 0,4,8,12
            float4 va = *(const float4*)(A  + (size_t)(row0 + r) * K + kk + c4);
            float4 vb = *(const float4*)(BT + (size_t)(col0 + r) * K + kk + c4);
            va.x = to_tf32(va.x); va.y = to_tf32(va.y);
            va.z = to_tf32(va.z); va.w = to_tf32(va.w);
            *(float4*)&As[s][r * SSTR + c4] = va;
            *(float4*)&Bs[s][r * SSTR + c4] = vb;
        }
    };

    const int nc = K / MBK;
    load_tile(0, 0);
    __syncthreads();

    for (int ch = 0; ch < nc; ++ch) {
        const int cur = ch & 1;
        if (ch + 1 < nc) load_tile(cur ^ 1, (ch + 1) * MBK);

        #pragma unroll
        for (int ks = 0; ks < 2; ++ks) {
            const int kb = ks * 8;
            // A fragments: 4 m-tiles x 4 regs
            uint32_t a[4][4];
            #pragma unroll
            for (int mt = 0; mt < 4; ++mt) {
                const int m = warp_m + mt * 16;
                const float* Ab = &As[cur][0];
                a[mt][0] = __float_as_uint(Ab[(m + g)     * SSTR + kb + t]);
                a[mt][1] = __float_as_uint(Ab[(m + g + 8) * SSTR + kb + t]);
                a[mt][2] = __float_as_uint(Ab[(m + g)     * SSTR + kb + t + 4]);
                a[mt][3] = __float_as_uint(Ab[(m + g + 8) * SSTR + kb + t + 4]);
            }
            // B fragments: 4 n-tiles x 2 regs
            uint32_t b[4][2];
            #pragma unroll
            for (int nt = 0; nt < 4; ++nt) {
                const int n = warp_n + nt * 8;
                const float* Bb = &Bs[cur][0];
                b[nt][0] = __float_as_uint(Bb[(n + g) * SSTR + kb + t]);
                b[nt][1] = __float_as_uint(Bb[(n + g) * SSTR + kb + t + 4]);
            }
            #pragma unroll
            for (int mt = 0; mt < 4; ++mt)
                #pragma unroll
                for (int nt = 0; nt < 4; ++nt)
                    mma_tf32(c[mt][nt][0], c[mt][nt][1], c[mt][nt][2], c[mt][nt][3],
                             a[mt][0], a[mt][1], a[mt][2], a[mt][3],
                             b[nt][0], b[nt][1]);
        }
        __syncthreads();
    }

    // ---- epilogue: c0,c1 -> row g, cols 2t,2t+1 ; c2,c3 -> row g+8 ----
    #pragma unroll
    for (int mt = 0; mt < 4; ++mt) {
        const int mb = row0 + warp_m + mt * 16;
        #pragma unroll
        for (int nt = 0; nt < 4; ++nt) {
            const int nb = col0 + warp_n + nt * 8 + 2 * t;
            const float b0 = bias[nb], b1 = bias[nb + 1];
            #pragma unroll
            for (int half = 0; half < 2; ++half) {
                const int r = mb + g + half * 8;
                float vx = c[mt][nt][2 * half + 0] + b0;
                float vy = c[mt][nt][2 * half + 1] + b1;
                if (EPI == EPI_GELU) { vx = gelu_exact(vx); vy = gelu_exact(vy); }
                if (EPI == EPI_RESID) {
                    const float2 rr = *(const float2*)(res + (size_t)r * N + nb);
                    vx += rr.x; vy += rr.y;
                }
                float2 o; o.x = vx; o.y = vy;
                *(float2*)(C + (size_t)r * N + nb) = o;
            }
        }
    }
}

// ---------------------------------------------------------------------------
// Flash attention (fp32, packed f32x2). One thread = one query row.
// ---------------------------------------------------------------------------
#define FA_BR 128
#define FA_BC 32

__global__ __launch_bounds__(128)
void flash_attn_kernel(const float* __restrict__ Q, const float* __restrict__ K,
                       const float* __restrict__ V, const int* __restrict__ mask,
                       float* __restrict__ O)
{
    const int bh = blockIdx.x;
    const int b  = bh >> 4;
    const int h  = bh & 15;
    const int tid = threadIdx.x;
    const int qi  = blockIdx.y * FA_BR + tid;

    const float* qptr  = Q + ((size_t)(b * SEQ + qi)) * DM + h * DK;
    const float* kbase = K + ((size_t)(b * SEQ)) * DM + h * DK;
    const float* vbase = V + ((size_t)(b * SEQ)) * DM + h * DK;

    unsigned long long q2[32], o2[32];
    #pragma unroll
    for (int d4 = 0; d4 < 16; d4++) {
        float4 v = *(const float4*)(qptr + 4 * d4);
        q2[2 * d4 + 0] = pack2(v.x * 0.125f, v.y * 0.125f);
        q2[2 * d4 + 1] = pack2(v.z * 0.125f, v.w * 0.125f);
        o2[2 * d4 + 0] = 0ull;
        o2[2 * d4 + 1] = 0ull;
    }

    float m = -1e30f, l = 0.f;

    __shared__ __align__(16) float Ks[FA_BC][DK];
    __shared__ __align__(16) float Vs[FA_BC][DK];
    __shared__ int ms[FA_BC];

    for (int kc = 0; kc < SEQ; kc += FA_BC) {
        __syncthreads();
        #pragma unroll
        for (int lu = 0; lu < 4; lu++) {
            int f  = tid + lu * 128;
            int r  = f >> 4;
            int c4 = (f & 15) << 2;
            *(float4*)&Ks[r][c4] = *(const float4*)(kbase + (size_t)(kc + r) * DM + c4);
            *(float4*)&Vs[r][c4] = *(const float4*)(vbase + (size_t)(kc + r) * DM + c4);
        }
        if (tid < FA_BC) ms[tid] = mask[b * SEQ + kc + tid];
        __syncthreads();

        float s[FA_BC];
        float tmax = -1e30f;
        #pragma unroll
        for (int j = 0; j < FA_BC; j++) {
            const ulonglong2* kj = (const ulonglong2*)&Ks[j][0];
            unsigned long long a0 = 0ull, a1 = 0ull, a2 = 0ull, a3 = 0ull;
            #pragma unroll
            for (int d4 = 0; d4 < 16; d4 += 2) {
                ulonglong2 k0 = kj[d4];
                ulonglong2 k1 = kj[d4 + 1];
                a0 = fma2(q2[2 * d4 + 0], k0.x, a0);
                a1 = fma2(q2[2 * d4 + 1], k0.y, a1);
                a2 = fma2(q2[2 * d4 + 2], k1.x, a2);
                a3 = fma2(q2[2 * d4 + 3], k1.y, a3);
            }
            float2 f0 = unpack2(a0), f1 = unpack2(a1);
            float2 f2 = unpack2(a2), f3 = unpack2(a3);
            float sc = ((f0.x + f0.y) + (f1.x + f1.y))
                     + ((f2.x + f2.y) + (f3.x + f3.y));
            if (ms[j] == 0) sc = -1e9f;
            s[j] = sc;
            tmax = fmaxf(tmax, sc);
        }

        const float m_new = fmaxf(m, tmax);
        const float corr  = __expf(m - m_new);
        l *= corr;
        const unsigned long long c2 = pack2(corr, corr);
        #pragma unroll
        for (int d = 0; d < 32; d++) o2[d] = mul2(o2[d], c2);

        #pragma unroll
        for (int j = 0; j < FA_BC; j++) {
            const float p = __expf(s[j] - m_new);
            l += p;
            const unsigned long long p2 = pack2(p, p);
            const ulonglong2* vj = (const ulonglong2*)&Vs[j][0];
            #pragma unroll
            for (int d4 = 0; d4 < 16; d4++) {
                ulonglong2 vv = vj[d4];
                o2[2 * d4 + 0] = fma2(p2, vv.x, o2[2 * d4 + 0]);
                o2[2 * d4 + 1] = fma2(p2, vv.y, o2[2 * d4 + 1]);
            }
        }
        m = m_new;
    }

    const float inv = 1.0f / l;
    float* optr = O + ((size_t)(b * SEQ + qi)) * DM + h * DK;
    #pragma unroll
    for (int d = 0; d < 32; d++) {
        float2 v = unpack2(o2[d]);
        v.x *= inv; v.y *= inv;
        *(float2*)&optr[2 * d] = v;
    }
}

// ---------------------------------------------------------------------------
// kernel_launch
// ---------------------------------------------------------------------------
extern "C" void kernel_launch(void* const* d_in, const int* in_sizes, int n_in,
                              void* d_out, int out_size)
{
    (void)in_sizes; (void)n_in; (void)out_size;
    const float* x     = (const float*)d_in[0];
    const int*   mask  = (const int*)  d_in[1];
    const float* Wq    = (const float*)d_in[2];
    const float* bq    = (const float*)d_in[3];
    const float* Wk    = (const float*)d_in[4];
    const float* bk    = (const float*)d_in[5];
    const float* Wv    = (const float*)d_in[6];
    const float* bv    = (const float*)d_in[7];
    const float* Wo    = (const float*)d_in[8];
    const float* bo    = (const float*)d_in[9];
    const float* W1    = (const float*)d_in[10];
    const float* b1    = (const float*)d_in[11];
    const float* W2    = (const float*)d_in[12];
    const float* b2    = (const float*)d_in[13];
    const float* ln1_g = (const float*)d_in[14];
    const float* ln1_b = (const float*)d_in[15];
    const float* ln2_g = (const float*)d_in[16];
    const float* ln2_b = (const float*)d_in[17];
    float* out = (float*)d_out;

    float *h, *q, *k, *v, *attn, *x2, *ff;
    float *wqT, *wkT, *wvT, *woT, *w1T, *w2T;
    cudaGetSymbolAddress((void**)&h,    g_h);
    cudaGetSymbolAddress((void**)&q,    g_q);
    cudaGetSymbolAddress((void**)&k,    g_k);
    cudaGetSymbolAddress((void**)&v,    g_v);
    cudaGetSymbolAddress((void**)&attn, g_attn);
    cudaGetSymbolAddress((void**)&x2,   g_x2);
    cudaGetSymbolAddress((void**)&ff,   g_ff);
    cudaGetSymbolAddress((void**)&wqT,  g_wqT);
    cudaGetSymbolAddress((void**)&wkT,  g_wkT);
    cudaGetSymbolAddress((void**)&wvT,  g_wvT);
    cudaGetSymbolAddress((void**)&woT,  g_woT);
    cudaGetSymbolAddress((void**)&w1T,  g_w1T);
    cudaGetSymbolAddress((void**)&w2T,  g_w2T);

    const dim3 tb(32, 8);
    transpose_tf32<<<dim3(DM  / 32, DM  / 32), tb>>>(Wq, wqT, DM,  DM);
    transpose_tf32<<<dim3(DM  / 32, DM  / 32), tb>>>(Wk, wkT, DM,  DM);
    transpose_tf32<<<dim3(DM  / 32, DM  / 32), tb>>>(Wv, wvT, DM,  DM);
    transpose_tf32<<<dim3(DM  / 32, DM  / 32), tb>>>(Wo, woT, DM,  DM);
    transpose_tf32<<<dim3(DFF / 32, DM  / 32), tb>>>(W1, w1T, DM,  DFF);
    transpose_tf32<<<dim3(DM  / 32, DFF / 32), tb>>>(W2, w2T, DFF, DM);

    const dim3 gD (DM  / 128, NTOK / 128);   // (8, 64)
    const dim3 gFF(DFF / 128, NTOK / 128);   // (32, 64)

    // 1) h = LN1(x)
    ln_kernel<<<NTOK, 256>>>(x, ln1_g, ln1_b, h);
    // 2) Q,K,V projections
    mma_gemm<EPI_BIAS><<<gD, 256>>>(h, wqT, bq, nullptr, q, NTOK, DM, DM);
    mma_gemm<EPI_BIAS><<<gD, 256>>>(h, wkT, bk, nullptr, k, NTOK, DM, DM);
    mma_gemm<EPI_BIAS><<<gD, 256>>>(h, wvT, bv, nullptr, v, NTOK, DM, DM);
    // 3) attention
    flash_attn_kernel<<<dim3(BSZ * NH, SEQ / FA_BR), 128>>>(q, k, v, mask, attn);
    // 4) x2 = x + attn @ Wo + bo
    mma_gemm<EPI_RESID><<<gD, 256>>>(attn, woT, bo, x, x2, NTOK, DM, DM);
    // 5) h = LN2(x2)
    ln_kernel<<<NTOK, 256>>>(x2, ln2_g, ln2_b, h);
    // 6) ff = gelu(h @ W1 + b1)
    mma_gemm<EPI_GELU><<<gFF, 256>>>(h, w1T, b1, nullptr, ff, NTOK, DFF, DM);
    // 7) out = x2 + ff @ W2 + b2
    mma_gemm<EPI_RESID><<<gD, 256>>>(ff, w2T, b2, x2, out, NTOK, DM, DFF);
}

// round 8
// speedup vs baseline: 2.0779x; 1.2665x over previous
#include <cuda_runtime.h>
#include <cuda_bf16.h>
#include <cstddef>
#include <cstdint>

// ---------------------------------------------------------------------------
// Problem constants
// ---------------------------------------------------------------------------
#define BSZ   4
#define SEQ   2048
#define DM    1024
#define NH    16
#define DK    64
#define DFF   4096
#define NTOK  (BSZ*SEQ)            // 8192
#define DQKV  (3*DM)               // 3072

// ---------------------------------------------------------------------------
// Scratch (device globals: allocation-free per harness rules)
// ---------------------------------------------------------------------------
__device__ float g_h   [(size_t)NTOK*DM];     // ln output (tf32-rounded)
__device__ float g_qkv [(size_t)NTOK*DQKV];   // fused qkv projections
__device__ float g_attn[(size_t)NTOK*DM];     // flash output (tf32-rounded)
__device__ float g_x2  [(size_t)NTOK*DM];
__device__ float g_ff  [(size_t)NTOK*DFF];    // gelu output (tf32-rounded)
// transposed (tf32-rounded) weights: WT[n][k]
__device__ float g_wqkvT[(size_t)DM*DQKV];
__device__ float g_woT  [(size_t)DM*DM];
__device__ float g_w1T  [(size_t)DM*DFF];
__device__ float g_w2T  [(size_t)DFF*DM];
__device__ float g_bqkv [DQKV];

// ---------------------------------------------------------------------------
// Helpers
// ---------------------------------------------------------------------------
__device__ __forceinline__ float to_tf32(float x) {
    float r;
    asm("cvt.rna.tf32.f32 %0, %1;" : "=f"(r) : "f"(x));
    return r;
}
__device__ __forceinline__ float gelu_exact(float v) {
    return 0.5f * v * (1.0f + erff(v * 0.70710678118654752440f));
}
__device__ __forceinline__ uint32_t smem_u32(const void* p) {
    uint32_t a;
    asm("{ .reg .u64 t; cvta.to.shared.u64 t, %1; cvt.u32.u64 %0, t; }"
        : "=r"(a) : "l"(p));
    return a;
}
__device__ __forceinline__ void cp_async16(uint32_t dst, const void* src) {
    asm volatile("cp.async.cg.shared.global [%0], [%1], 16;"
                 :: "r"(dst), "l"(src) : "memory");
}
__device__ __forceinline__ void cp_commit() {
    asm volatile("cp.async.commit_group;" ::: "memory");
}
template<int N>
__device__ __forceinline__ void cp_wait() {
    asm volatile("cp.async.wait_group %0;" :: "n"(N) : "memory");
}

// legacy tensor-core mma (sm_80+; compiles under plain sm_103 target)
__device__ __forceinline__ void mma_tf32(float& c0, float& c1, float& c2, float& c3,
                                         uint32_t a0, uint32_t a1, uint32_t a2, uint32_t a3,
                                         uint32_t b0, uint32_t b1) {
    asm volatile(
        "mma.sync.aligned.m16n8k8.row.col.f32.tf32.tf32.f32 "
        "{%0,%1,%2,%3}, {%4,%5,%6,%7}, {%8,%9}, {%0,%1,%2,%3};"
        : "+f"(c0), "+f"(c1), "+f"(c2), "+f"(c3)
        : "r"(a0), "r"(a1), "r"(a2), "r"(a3), "r"(b0), "r"(b1));
}

// packed f32x2 (for flash attention)
__device__ __forceinline__ unsigned long long pack2(float lo, float hi) {
    unsigned long long r;
    asm("mov.b64 %0, {%1, %2};" : "=l"(r) : "f"(lo), "f"(hi));
    return r;
}
__device__ __forceinline__ float2 unpack2(unsigned long long v) {
    float2 r;
    asm("mov.b64 {%0, %1}, %2;" : "=f"(r.x), "=f"(r.y) : "l"(v));
    return r;
}
__device__ __forceinline__ unsigned long long fma2(unsigned long long a,
                                                   unsigned long long b,
                                                   unsigned long long c) {
    unsigned long long d;
    asm("fma.rn.f32x2 %0, %1, %2, %3;" : "=l"(d) : "l"(a), "l"(b), "l"(c));
    return d;
}
__device__ __forceinline__ unsigned long long mul2(unsigned long long a,
                                                   unsigned long long b) {
    unsigned long long d;
    asm("mul.rn.f32x2 %0, %1, %2;" : "=l"(d) : "l"(a), "l"(b));
    return d;
}

// ---------------------------------------------------------------------------
// Weight transpose with tf32 rounding: W[K][N] -> WT[N][K]
// ---------------------------------------------------------------------------
__global__ __launch_bounds__(256)
void transpose_tf32(const float* __restrict__ W, float* __restrict__ WT, int K, int N)
{
    __shared__ float t[32][33];
    const int tx = threadIdx.x, ty = threadIdx.y;
    const int n0 = blockIdx.x * 32, k0 = blockIdx.y * 32;
    #pragma unroll
    for (int j = ty; j < 32; j += 8)
        t[j][tx] = to_tf32(W[(size_t)(k0 + j) * N + n0 + tx]);
    __syncthreads();
    #pragma unroll
    for (int j = ty; j < 32; j += 8)
        WT[(size_t)(n0 + j) * K + k0 + tx] = t[tx][j];
}

__global__ __launch_bounds__(256)
void concat_bias(const float* __restrict__ bq, const float* __restrict__ bk,
                 const float* __restrict__ bv, float* __restrict__ o)
{
    const int i = blockIdx.x * 256 + threadIdx.x;
    if (i < DM)            o[i] = bq[i];
    else if (i < 2 * DM)   o[i] = bk[i - DM];
    else if (i < 3 * DM)   o[i] = bv[i - 2 * DM];
}

// ---------------------------------------------------------------------------
// LayerNorm: one block (256 thr) per token; output tf32-rounded (GEMM A input)
// ---------------------------------------------------------------------------
__global__ __launch_bounds__(256)
void ln_kernel(const float* __restrict__ x, const float* __restrict__ g,
               const float* __restrict__ b, float* __restrict__ y)
{
    const int t = blockIdx.x;
    const int i = threadIdx.x;
    const float* xp = x + (size_t)t * DM;

    float4 v = *(const float4*)(xp + i * 4);
    float s  = (v.x + v.y) + (v.z + v.w);
    float ss = fmaf(v.x, v.x, fmaf(v.y, v.y, fmaf(v.z, v.z, v.w * v.w)));

    #pragma unroll
    for (int o = 16; o > 0; o >>= 1) {
        s  += __shfl_xor_sync(0xFFFFFFFFu, s,  o);
        ss += __shfl_xor_sync(0xFFFFFFFFu, ss, o);
    }
    __shared__ float sh[16];
    const int w = i >> 5;
    if ((i & 31) == 0) { sh[w] = s; sh[8 + w] = ss; }
    __syncthreads();
    float S = 0.f, SS = 0.f;
    #pragma unroll
    for (int k = 0; k < 8; k++) { S += sh[k]; SS += sh[8 + k]; }

    const float mean = S * (1.0f / DM);
    const float var  = SS * (1.0f / DM) - mean * mean;
    const float r    = rsqrtf(var + 1e-5f);

    float4 gg = *(const float4*)(g + i * 4);
    float4 bb = *(const float4*)(b + i * 4);
    float4 o;
    o.x = to_tf32((v.x - mean) * r * gg.x + bb.x);
    o.y = to_tf32((v.y - mean) * r * gg.y + bb.y);
    o.z = to_tf32((v.z - mean) * r * gg.z + bb.z);
    o.w = to_tf32((v.w - mean) * r * gg.w + bb.w);
    *(float4*)(y + (size_t)t * DM + i * 4) = o;
}

// ---------------------------------------------------------------------------
// TF32 mma.sync GEMM with cp.async 3-stage pipeline.
// C[M,N] = A[M,K] @ BT[N,K]^T + bias (+epilogue)
// CTA tile 128x128, 8 warps (2x4), warp tile 64x32 (4x4 m16n8k8 frags).
// A and BT must already be tf32-rounded (producers round).
// ---------------------------------------------------------------------------
#define EPI_BIAS  0
#define EPI_RESID 1
#define EPI_GELU  2

#define MBK     16
#define SSTR    20                 // padded row stride in floats
#define TSZ     (128 * SSTR)       // floats per tile buffer
#define STAGES  3
#define GSMEM   (STAGES * 2 * TSZ * 4)   // bytes

template<int EPI>
__global__ __launch_bounds__(256)
void mma_gemm(const float* __restrict__ A, const float* __restrict__ BT,
              const float* __restrict__ bias, const float* __restrict__ res,
              float* __restrict__ C, int M, int N, int K)
{
    extern __shared__ __align__(16) float sm[];
    float* Asm = sm;                 // STAGES tiles
    float* Bsm = sm + STAGES * TSZ;  // STAGES tiles

    const int tid  = threadIdx.x;
    const int wid  = tid >> 5;
    const int lane = tid & 31;
    const int g    = lane >> 2;
    const int t    = lane & 3;

    const int warp_m = (wid & 1) * 64;
    const int warp_n = (wid >> 1) * 32;
    const int row0 = blockIdx.y * 128;
    const int col0 = blockIdx.x * 128;

    // per-thread load coords: 2 float4 per matrix per stage
    const int r0 = tid >> 2;                 // 0..63
    const int c40 = (tid & 3) * 4;           // 0,4,8,12
    const int r1 = (tid + 256) >> 2;         // 64..127
    const uint32_t asm_base = smem_u32(Asm);
    const uint32_t bsm_base = smem_u32(Bsm);

    auto issue_load = [&](int stage, int kk) {
        const uint32_t ao = asm_base + (uint32_t)stage * TSZ * 4;
        const uint32_t bo = bsm_base + (uint32_t)stage * TSZ * 4;
        cp_async16(ao + (r0 * SSTR + c40) * 4, A  + (size_t)(row0 + r0) * K + kk + c40);
        cp_async16(ao + (r1 * SSTR + c40) * 4, A  + (size_t)(row0 + r1) * K + kk + c40);
        cp_async16(bo + (r0 * SSTR + c40) * 4, BT + (size_t)(col0 + r0) * K + kk + c40);
        cp_async16(bo + (r1 * SSTR + c40) * 4, BT + (size_t)(col0 + r1) * K + kk + c40);
    };

    float c[4][4][4];
    #pragma unroll
    for (int i = 0; i < 4; i++)
        #pragma unroll
        for (int j = 0; j < 4; j++)
            #pragma unroll
            for (int q = 0; q < 4; q++) c[i][j][q] = 0.f;

    const int nc = K / MBK;

    // prologue: stages 0..STAGES-2
    #pragma unroll
    for (int s = 0; s < STAGES - 1; ++s) {
        if (s < nc) issue_load(s, s * MBK);
        cp_commit();
    }

    for (int ch = 0; ch < nc; ++ch) {
        cp_wait<STAGES - 2>();
        __syncthreads();

        // issue load for stage ch+STAGES-1 (buffer (ch-1)%STAGES, freed by the sync)
        if (ch + STAGES - 1 < nc) issue_load((ch + STAGES - 1) % STAGES, (ch + STAGES - 1) * MBK);
        cp_commit();

        const float* Ab = Asm + (ch % STAGES) * TSZ;
        const float* Bb = Bsm + (ch % STAGES) * TSZ;

        #pragma unroll
        for (int ks = 0; ks < 2; ++ks) {
            const int kb = ks * 8;
            uint32_t a[4][4];
            #pragma unroll
            for (int mt = 0; mt < 4; ++mt) {
                const int m = warp_m + mt * 16;
                a[mt][0] = __float_as_uint(Ab[(m + g)     * SSTR + kb + t]);
                a[mt][1] = __float_as_uint(Ab[(m + g + 8) * SSTR + kb + t]);
                a[mt][2] = __float_as_uint(Ab[(m + g)     * SSTR + kb + t + 4]);
                a[mt][3] = __float_as_uint(Ab[(m + g + 8) * SSTR + kb + t + 4]);
            }
            uint32_t b[4][2];
            #pragma unroll
            for (int nt = 0; nt < 4; ++nt) {
                const int n = warp_n + nt * 8;
                b[nt][0] = __float_as_uint(Bb[(n + g) * SSTR + kb + t]);
                b[nt][1] = __float_as_uint(Bb[(n + g) * SSTR + kb + t + 4]);
            }
            #pragma unroll
            for (int mt = 0; mt < 4; ++mt)
                #pragma unroll
                for (int nt = 0; nt < 4; ++nt)
                    mma_tf32(c[mt][nt][0], c[mt][nt][1], c[mt][nt][2], c[mt][nt][3],
                             a[mt][0], a[mt][1], a[mt][2], a[mt][3],
                             b[nt][0], b[nt][1]);
        }
        __syncthreads();
    }

    // ---- epilogue ----
    #pragma unroll
    for (int mt = 0; mt < 4; ++mt) {
        const int mb = row0 + warp_m + mt * 16;
        #pragma unroll
        for (int nt = 0; nt < 4; ++nt) {
            const int nb = col0 + warp_n + nt * 8 + 2 * t;
            const float b0 = bias[nb], b1 = bias[nb + 1];
            #pragma unroll
            for (int half = 0; half < 2; ++half) {
                const int r = mb + g + half * 8;
                float vx = c[mt][nt][2 * half + 0] + b0;
                float vy = c[mt][nt][2 * half + 1] + b1;
                if (EPI == EPI_GELU) {
                    vx = to_tf32(gelu_exact(vx));   // feeds FFN2 A operand
                    vy = to_tf32(gelu_exact(vy));
                }
                if (EPI == EPI_RESID) {
                    const float2 rr = *(const float2*)(res + (size_t)r * N + nb);
                    vx += rr.x; vy += rr.y;
                }
                float2 o; o.x = vx; o.y = vy;
                *(float2*)(C + (size_t)r * N + nb) = o;
            }
        }
    }
}

// ---------------------------------------------------------------------------
// Flash attention (fp32, packed f32x2) on fused qkv buffer (row stride 3072).
// One thread = one query row. Output tf32-rounded (feeds O-proj A operand).
// ---------------------------------------------------------------------------
#define FA_BR 128
#define FA_BC 32

__global__ __launch_bounds__(128)
void flash_attn_kernel(const float* __restrict__ QKV, const int* __restrict__ mask,
                       float* __restrict__ O)
{
    const int bh = blockIdx.x;
    const int b  = bh >> 4;
    const int h  = bh & 15;
    const int tid = threadIdx.x;
    const int qi  = blockIdx.y * FA_BR + tid;

    const float* qptr  = QKV + ((size_t)(b * SEQ + qi)) * DQKV + h * DK;
    const float* kbase = QKV + ((size_t)(b * SEQ)) * DQKV + DM + h * DK;
    const float* vbase = QKV + ((size_t)(b * SEQ)) * DQKV + 2 * DM + h * DK;

    unsigned long long q2[32], o2[32];
    #pragma unroll
    for (int d4 = 0; d4 < 16; d4++) {
        float4 v = *(const float4*)(qptr + 4 * d4);
        q2[2 * d4 + 0] = pack2(v.x * 0.125f, v.y * 0.125f);
        q2[2 * d4 + 1] = pack2(v.z * 0.125f, v.w * 0.125f);
        o2[2 * d4 + 0] = 0ull;
        o2[2 * d4 + 1] = 0ull;
    }

    float m = -1e30f, l = 0.f;

    __shared__ __align__(16) float Ks[FA_BC][DK];
    __shared__ __align__(16) float Vs[FA_BC][DK];
    __shared__ int ms[FA_BC];

    for (int kc = 0; kc < SEQ; kc += FA_BC) {
        __syncthreads();
        #pragma unroll
        for (int lu = 0; lu < 4; lu++) {
            int f  = tid + lu * 128;
            int r  = f >> 4;
            int c4 = (f & 15) << 2;
            *(float4*)&Ks[r][c4] = *(const float4*)(kbase + (size_t)(kc + r) * DQKV + c4);
            *(float4*)&Vs[r][c4] = *(const float4*)(vbase + (size_t)(kc + r) * DQKV + c4);
        }
        if (tid < FA_BC) ms[tid] = mask[b * SEQ + kc + tid];
        __syncthreads();

        float s[FA_BC];
        float tmax = -1e30f;
        #pragma unroll
        for (int j = 0; j < FA_BC; j++) {
            const ulonglong2* kj = (const ulonglong2*)&Ks[j][0];
            unsigned long long a0 = 0ull, a1 = 0ull, a2 = 0ull, a3 = 0ull;
            #pragma unroll
            for (int d4 = 0; d4 < 16; d4 += 2) {
                ulonglong2 k0 = kj[d4];
                ulonglong2 k1 = kj[d4 + 1];
                a0 = fma2(q2[2 * d4 + 0], k0.x, a0);
                a1 = fma2(q2[2 * d4 + 1], k0.y, a1);
                a2 = fma2(q2[2 * d4 + 2], k1.x, a2);
                a3 = fma2(q2[2 * d4 + 3], k1.y, a3);
            }
            float2 f0 = unpack2(a0), f1 = unpack2(a1);
            float2 f2 = unpack2(a2), f3 = unpack2(a3);
            float sc = ((f0.x + f0.y) + (f1.x + f1.y))
                     + ((f2.x + f2.y) + (f3.x + f3.y));
            if (ms[j] == 0) sc = -1e9f;
            s[j] = sc;
            tmax = fmaxf(tmax, sc);
        }

        const float m_new = fmaxf(m, tmax);
        const float corr  = __expf(m - m_new);
        l *= corr;
        const unsigned long long c2 = pack2(corr, corr);
        #pragma unroll
        for (int d = 0; d < 32; d++) o2[d] = mul2(o2[d], c2);

        #pragma unroll
        for (int j = 0; j < FA_BC; j++) {
            const float p = __expf(s[j] - m_new);
            l += p;
            const unsigned long long p2 = pack2(p, p);
            const ulonglong2* vj = (const ulonglong2*)&Vs[j][0];
            #pragma unroll
            for (int d4 = 0; d4 < 16; d4++) {
                ulonglong2 vv = vj[d4];
                o2[2 * d4 + 0] = fma2(p2, vv.x, o2[2 * d4 + 0]);
                o2[2 * d4 + 1] = fma2(p2, vv.y, o2[2 * d4 + 1]);
            }
        }
        m = m_new;
    }

    const float inv = 1.0f / l;
    float* optr = O + ((size_t)(b * SEQ + qi)) * DM + h * DK;
    #pragma unroll
    for (int d = 0; d < 32; d++) {
        float2 v = unpack2(o2[d]);
        v.x = to_tf32(v.x * inv);   // feeds O-proj A operand
        v.y = to_tf32(v.y * inv);
        *(float2*)&optr[2 * d] = v;
    }
}

// ---------------------------------------------------------------------------
// kernel_launch
// ---------------------------------------------------------------------------
extern "C" void kernel_launch(void* const* d_in, const int* in_sizes, int n_in,
                              void* d_out, int out_size)
{
    (void)in_sizes; (void)n_in; (void)out_size;
    const float* x     = (const float*)d_in[0];
    const int*   mask  = (const int*)  d_in[1];
    const float* Wq    = (const float*)d_in[2];
    const float* bq    = (const float*)d_in[3];
    const float* Wk    = (const float*)d_in[4];
    const float* bk    = (const float*)d_in[5];
    const float* Wv    = (const float*)d_in[6];
    const float* bv    = (const float*)d_in[7];
    const float* Wo    = (const float*)d_in[8];
    const float* bo    = (const float*)d_in[9];
    const float* W1    = (const float*)d_in[10];
    const float* b1    = (const float*)d_in[11];
    const float* W2    = (const float*)d_in[12];
    const float* b2    = (const float*)d_in[13];
    const float* ln1_g = (const float*)d_in[14];
    const float* ln1_b = (const float*)d_in[15];
    const float* ln2_g = (const float*)d_in[16];
    const float* ln2_b = (const float*)d_in[17];
    float* out = (float*)d_out;

    float *h, *qkv, *attn, *x2, *ff;
    float *wqkvT, *woT, *w1T, *w2T, *bqkv;
    cudaGetSymbolAddress((void**)&h,     g_h);
    cudaGetSymbolAddress((void**)&qkv,   g_qkv);
    cudaGetSymbolAddress((void**)&attn,  g_attn);
    cudaGetSymbolAddress((void**)&x2,    g_x2);
    cudaGetSymbolAddress((void**)&ff,    g_ff);
    cudaGetSymbolAddress((void**)&wqkvT, g_wqkvT);
    cudaGetSymbolAddress((void**)&woT,   g_woT);
    cudaGetSymbolAddress((void**)&w1T,   g_w1T);
    cudaGetSymbolAddress((void**)&w2T,   g_w2T);
    cudaGetSymbolAddress((void**)&bqkv,  g_bqkv);

    cudaFuncSetAttribute(mma_gemm<EPI_BIAS>,  cudaFuncAttributeMaxDynamicSharedMemorySize, GSMEM);
    cudaFuncSetAttribute(mma_gemm<EPI_RESID>, cudaFuncAttributeMaxDynamicSharedMemorySize, GSMEM);
    cudaFuncSetAttribute(mma_gemm<EPI_GELU>,  cudaFuncAttributeMaxDynamicSharedMemorySize, GSMEM);

    const dim3 tb(32, 8);
    // fused qkv weight: sections [0:1024)=Wq, [1024:2048)=Wk, [2048:3072)=Wv
    transpose_tf32<<<dim3(DM  / 32, DM  / 32), tb>>>(Wq, wqkvT,                      DM,  DM);
    transpose_tf32<<<dim3(DM  / 32, DM  / 32), tb>>>(Wk, wqkvT + (size_t)DM * DM,    DM,  DM);
    transpose_tf32<<<dim3(DM  / 32, DM  / 32), tb>>>(Wv, wqkvT + (size_t)2 * DM * DM, DM, DM);
    transpose_tf32<<<dim3(DM  / 32, DM  / 32), tb>>>(Wo, woT, DM,  DM);
    transpose_tf32<<<dim3(DFF / 32, DM  / 32), tb>>>(W1, w1T, DM,  DFF);
    transpose_tf32<<<dim3(DM  / 32, DFF / 32), tb>>>(W2, w2T, DFF, DM);
    concat_bias<<<(DQKV + 255) / 256, 256>>>(bq, bk, bv, bqkv);

    const dim3 gQKV(DQKV / 128, NTOK / 128);   // (24, 64)
    const dim3 gD  (DM   / 128, NTOK / 128);   // (8, 64)
    const dim3 gFF (DFF  / 128, NTOK / 128);   // (32, 64)

    // 1) h = LN1(x)  (tf32-rounded)
    ln_kernel<<<NTOK, 256>>>(x, ln1_g, ln1_b, h);
    // 2) fused QKV projection
    mma_gemm<EPI_BIAS><<<gQKV, 256, GSMEM>>>(h, wqkvT, bqkv, nullptr, qkv, NTOK, DQKV, DM);
    // 3) attention (output tf32-rounded)
    flash_attn_kernel<<<dim3(BSZ * NH, SEQ / FA_BR), 128>>>(qkv, mask, attn);
    // 4) x2 = x + attn @ Wo + bo
    mma_gemm<EPI_RESID><<<gD, 256, GSMEM>>>(attn, woT, bo, x, x2, NTOK, DM, DM);
    // 5) h = LN2(x2)  (tf32-rounded)
    ln_kernel<<<NTOK, 256>>>(x2, ln2_g, ln2_b, h);
    // 6) ff = gelu(h @ W1 + b1)  (tf32-rounded)
    mma_gemm<EPI_GELU><<<gFF, 256, GSMEM>>>(h, w1T, b1, nullptr, ff, NTOK, DFF, DM);
    // 7) out = x2 + ff @ W2 + b2
    mma_gemm<EPI_RESID><<<gD, 256, GSMEM>>>(ff, w2T, b2, x2, out, NTOK, DM, DFF);
}

// round 13
// speedup vs baseline: 3.3729x; 1.6232x over previous
#include <cuda_runtime.h>
#include <cuda_bf16.h>
#include <cstddef>
#include <cstdint>

// ---------------------------------------------------------------------------
// Problem constants
// ---------------------------------------------------------------------------
#define BSZ   4
#define SEQ   2048
#define DM    1024
#define NH    16
#define DK    64
#define DFF   4096
#define NTOK  (BSZ*SEQ)            // 8192
#define DQKV  (3*DM)               // 3072

// ---------------------------------------------------------------------------
// Scratch (device globals: allocation-free per harness rules)
// ---------------------------------------------------------------------------
__device__ float g_h   [(size_t)NTOK*DM];     // ln output (tf32-rounded)
__device__ float g_qkv [(size_t)NTOK*DQKV];   // fused qkv projections (tf32)
__device__ float g_attn[(size_t)NTOK*DM];     // flash output (tf32-rounded)
__device__ float g_x2  [(size_t)NTOK*DM];
__device__ float g_ff  [(size_t)NTOK*DFF];    // gelu output (tf32-rounded)
// transposed (tf32-rounded) weights: WT[n][k]
__device__ float g_wqkvT[(size_t)DM*DQKV];
__device__ float g_woT  [(size_t)DM*DM];
__device__ float g_w1T  [(size_t)DM*DFF];
__device__ float g_w2T  [(size_t)DFF*DM];
__device__ float g_bqkv [DQKV];

// ---------------------------------------------------------------------------
// Helpers
// ---------------------------------------------------------------------------
__device__ __forceinline__ float to_tf32(float x) {
    float r;
    asm("cvt.rna.tf32.f32 %0, %1;" : "=f"(r) : "f"(x));
    return r;
}
__device__ __forceinline__ float gelu_exact(float v) {
    return 0.5f * v * (1.0f + erff(v * 0.70710678118654752440f));
}
__device__ __forceinline__ uint32_t smem_u32(const void* p) {
    uint32_t a;
    asm("{ .reg .u64 t; cvta.to.shared.u64 t, %1; cvt.u32.u64 %0, t; }"
        : "=r"(a) : "l"(p));
    return a;
}
__device__ __forceinline__ void cp_async16(uint32_t dst, const void* src) {
    asm volatile("cp.async.cg.shared.global [%0], [%1], 16;"
                 :: "r"(dst), "l"(src) : "memory");
}
__device__ __forceinline__ void cp_commit() {
    asm volatile("cp.async.commit_group;" ::: "memory");
}
template<int N>
__device__ __forceinline__ void cp_wait() {
    asm volatile("cp.async.wait_group %0;" :: "n"(N) : "memory");
}

// legacy tensor-core mma (sm_80+; compiles under plain sm_103 target)
__device__ __forceinline__ void mma_tf32(float& c0, float& c1, float& c2, float& c3,
                                         uint32_t a0, uint32_t a1, uint32_t a2, uint32_t a3,
                                         uint32_t b0, uint32_t b1) {
    asm volatile(
        "mma.sync.aligned.m16n8k8.row.col.f32.tf32.tf32.f32 "
        "{%0,%1,%2,%3}, {%4,%5,%6,%7}, {%8,%9}, {%0,%1,%2,%3};"
        : "+f"(c0), "+f"(c1), "+f"(c2), "+f"(c3)
        : "r"(a0), "r"(a1), "r"(a2), "r"(a3), "r"(b0), "r"(b1));
}

// ---------------------------------------------------------------------------
// Weight transpose with tf32 rounding: W[K][N] -> WT[N][K]
// ---------------------------------------------------------------------------
__global__ __launch_bounds__(256)
void transpose_tf32(const float* __restrict__ W, float* __restrict__ WT, int K, int N)
{
    __shared__ float t[32][33];
    const int tx = threadIdx.x, ty = threadIdx.y;
    const int n0 = blockIdx.x * 32, k0 = blockIdx.y * 32;
    #pragma unroll
    for (int j = ty; j < 32; j += 8)
        t[j][tx] = to_tf32(W[(size_t)(k0 + j) * N + n0 + tx]);
    __syncthreads();
    #pragma unroll
    for (int j = ty; j < 32; j += 8)
        WT[(size_t)(n0 + j) * K + k0 + tx] = t[tx][j];
}

__global__ __launch_bounds__(256)
void concat_bias(const float* __restrict__ bq, const float* __restrict__ bk,
                 const float* __restrict__ bv, float* __restrict__ o)
{
    const int i = blockIdx.x * 256 + threadIdx.x;
    if (i < DM)            o[i] = bq[i];
    else if (i < 2 * DM)   o[i] = bk[i - DM];
    else if (i < 3 * DM)   o[i] = bv[i - 2 * DM];
}

// ---------------------------------------------------------------------------
// LayerNorm: one block (256 thr) per token; output tf32-rounded (GEMM A input)
// ---------------------------------------------------------------------------
__global__ __launch_bounds__(256)
void ln_kernel(const float* __restrict__ x, const float* __restrict__ g,
               const float* __restrict__ b, float* __restrict__ y)
{
    const int t = blockIdx.x;
    const int i = threadIdx.x;
    const float* xp = x + (size_t)t * DM;

    float4 v = *(const float4*)(xp + i * 4);
    float s  = (v.x + v.y) + (v.z + v.w);
    float ss = fmaf(v.x, v.x, fmaf(v.y, v.y, fmaf(v.z, v.z, v.w * v.w)));

    #pragma unroll
    for (int o = 16; o > 0; o >>= 1) {
        s  += __shfl_xor_sync(0xFFFFFFFFu, s,  o);
        ss += __shfl_xor_sync(0xFFFFFFFFu, ss, o);
    }
    __shared__ float sh[16];
    const int w = i >> 5;
    if ((i & 31) == 0) { sh[w] = s; sh[8 + w] = ss; }
    __syncthreads();
    float S = 0.f, SS = 0.f;
    #pragma unroll
    for (int k = 0; k < 8; k++) { S += sh[k]; SS += sh[8 + k]; }

    const float mean = S * (1.0f / DM);
    const float var  = SS * (1.0f / DM) - mean * mean;
    const float r    = rsqrtf(var + 1e-5f);

    float4 gg = *(const float4*)(g + i * 4);
    float4 bb = *(const float4*)(b + i * 4);
    float4 o;
    o.x = to_tf32((v.x - mean) * r * gg.x + bb.x);
    o.y = to_tf32((v.y - mean) * r * gg.y + bb.y);
    o.z = to_tf32((v.z - mean) * r * gg.z + bb.z);
    o.w = to_tf32((v.w - mean) * r * gg.w + bb.w);
    *(float4*)(y + (size_t)t * DM + i * 4) = o;
}

// ---------------------------------------------------------------------------
// TF32 mma.sync GEMM with cp.async 3-stage pipeline.
// C[M,N] = A[M,K] @ BT[N,K]^T + bias (+epilogue)
// ---------------------------------------------------------------------------
#define EPI_BIAS  0   // + bias, tf32-round (feeds flash tensor ops)
#define EPI_RESID 1   // + bias + residual (full fp32)
#define EPI_GELU  2   // + bias, gelu, tf32-round (feeds FFN2)

#define MBK     16
#define SSTR    20                 // padded row stride in floats
#define TSZ     (128 * SSTR)       // floats per tile buffer
#define STAGES  3
#define GSMEM   (STAGES * 2 * TSZ * 4)   // bytes

template<int EPI>
__global__ __launch_bounds__(256)
void mma_gemm(const float* __restrict__ A, const float* __restrict__ BT,
              const float* __restrict__ bias, const float* __restrict__ res,
              float* __restrict__ C, int M, int N, int K)
{
    extern __shared__ __align__(16) float sm[];
    float* Asm = sm;
    float* Bsm = sm + STAGES * TSZ;

    const int tid  = threadIdx.x;
    const int wid  = tid >> 5;
    const int lane = tid & 31;
    const int g    = lane >> 2;
    const int t    = lane & 3;

    const int warp_m = (wid & 1) * 64;
    const int warp_n = (wid >> 1) * 32;
    const int row0 = blockIdx.y * 128;
    const int col0 = blockIdx.x * 128;

    const int r0 = tid >> 2;
    const int c40 = (tid & 3) * 4;
    const int r1 = (tid + 256) >> 2;
    const uint32_t asm_base = smem_u32(Asm);
    const uint32_t bsm_base = smem_u32(Bsm);

    auto issue_load = [&](int stage, int kk) {
        const uint32_t ao = asm_base + (uint32_t)stage * TSZ * 4;
        const uint32_t bo = bsm_base + (uint32_t)stage * TSZ * 4;
        cp_async16(ao + (r0 * SSTR + c40) * 4, A  + (size_t)(row0 + r0) * K + kk + c40);
        cp_async16(ao + (r1 * SSTR + c40) * 4, A  + (size_t)(row0 + r1) * K + kk + c40);
        cp_async16(bo + (r0 * SSTR + c40) * 4, BT + (size_t)(col0 + r0) * K + kk + c40);
        cp_async16(bo + (r1 * SSTR + c40) * 4, BT + (size_t)(col0 + r1) * K + kk + c40);
    };

    float c[4][4][4];
    #pragma unroll
    for (int i = 0; i < 4; i++)
        #pragma unroll
        for (int j = 0; j < 4; j++)
            #pragma unroll
            for (int q = 0; q < 4; q++) c[i][j][q] = 0.f;

    const int nc = K / MBK;

    #pragma unroll
    for (int s = 0; s < STAGES - 1; ++s) {
        if (s < nc) issue_load(s, s * MBK);
        cp_commit();
    }

    for (int ch = 0; ch < nc; ++ch) {
        cp_wait<STAGES - 2>();
        __syncthreads();

        if (ch + STAGES - 1 < nc) issue_load((ch + STAGES - 1) % STAGES, (ch + STAGES - 1) * MBK);
        cp_commit();

        const float* Ab = Asm + (ch % STAGES) * TSZ;
        const float* Bb = Bsm + (ch % STAGES) * TSZ;

        #pragma unroll
        for (int ks = 0; ks < 2; ++ks) {
            const int kb = ks * 8;
            uint32_t a[4][4];
            #pragma unroll
            for (int mt = 0; mt < 4; ++mt) {
                const int m = warp_m + mt * 16;
                a[mt][0] = __float_as_uint(Ab[(m + g)     * SSTR + kb + t]);
                a[mt][1] = __float_as_uint(Ab[(m + g + 8) * SSTR + kb + t]);
                a[mt][2] = __float_as_uint(Ab[(m + g)     * SSTR + kb + t + 4]);
                a[mt][3] = __float_as_uint(Ab[(m + g + 8) * SSTR + kb + t + 4]);
            }
            uint32_t b[4][2];
            #pragma unroll
            for (int nt = 0; nt < 4; ++nt) {
                const int n = warp_n + nt * 8;
                b[nt][0] = __float_as_uint(Bb[(n + g) * SSTR + kb + t]);
                b[nt][1] = __float_as_uint(Bb[(n + g) * SSTR + kb + t + 4]);
            }
            #pragma unroll
            for (int mt = 0; mt < 4; ++mt)
                #pragma unroll
                for (int nt = 0; nt < 4; ++nt)
                    mma_tf32(c[mt][nt][0], c[mt][nt][1], c[mt][nt][2], c[mt][nt][3],
                             a[mt][0], a[mt][1], a[mt][2], a[mt][3],
                             b[nt][0], b[nt][1]);
        }
        __syncthreads();
    }

    #pragma unroll
    for (int mt = 0; mt < 4; ++mt) {
        const int mb = row0 + warp_m + mt * 16;
        #pragma unroll
        for (int nt = 0; nt < 4; ++nt) {
            const int nb = col0 + warp_n + nt * 8 + 2 * t;
            const float b0 = bias[nb], b1 = bias[nb + 1];
            #pragma unroll
            for (int half = 0; half < 2; ++half) {
                const int r = mb + g + half * 8;
                float vx = c[mt][nt][2 * half + 0] + b0;
                float vy = c[mt][nt][2 * half + 1] + b1;
                if (EPI == EPI_BIAS) {
                    vx = to_tf32(vx);               // feeds flash tensor ops
                    vy = to_tf32(vy);
                }
                if (EPI == EPI_GELU) {
                    vx = to_tf32(gelu_exact(vx));   // feeds FFN2 A operand
                    vy = to_tf32(gelu_exact(vy));
                }
                if (EPI == EPI_RESID) {
                    const float2 rr = *(const float2*)(res + (size_t)r * N + nb);
                    vx += rr.x; vy += rr.y;
                }
                float2 o; o.x = vx; o.y = vy;
                *(float2*)(C + (size_t)r * N + nb) = o;
            }
        }
    }
}

// ---------------------------------------------------------------------------
// Tensor-core flash attention (tf32 mma.sync).
// CTA = (b, h, 128-query tile). 8 warps; warp owns 16 query rows end-to-end.
// Per 64-key chunk: S = Q@K^T (mma) -> online softmax (regs + quad shfl)
//                   -> P to warp-local SMEM (tf32) -> O += P@V (mma).
// K/V/mask double-buffered via cp.async.
// ---------------------------------------------------------------------------
#define FAQ   128
#define FAC   64
#define QSTR  68     // Q/P smem row stride (floats): banks 4g+t, conflict-free
#define KSTR  68     // K smem row stride
#define VSTR  72     // V smem row stride: strided B-read banks 8t+g, conflict-free
#define FA_PS_F   (FAQ * QSTR)        // 8704 floats (Q tile, later P tile)
#define FA_KS_F   (FAC * KSTR)        // 4352 floats per stage
#define FA_VS_F   (FAC * VSTR)        // 4608 floats per stage
#define FA_SMEM   ((FA_PS_F + 2*FA_KS_F + 2*FA_VS_F) * 4 + 2*FAC*4)

__global__ __launch_bounds__(256)
void flash_mma_kernel(const float* __restrict__ QKV, const int* __restrict__ mask,
                      float* __restrict__ O)
{
    extern __shared__ __align__(16) float fsm[];
    float* Ps = fsm;                       // Q tile, then P tile (warp-local rows)
    float* Ks = fsm + FA_PS_F;             // 2 stages
    float* Vs = Ks + 2 * FA_KS_F;          // 2 stages
    int*   ms = (int*)(Vs + 2 * FA_VS_F);  // 2 stages x 64

    const int bh = blockIdx.x;
    const int b  = bh >> 4;
    const int h  = bh & 15;
    const int q0 = blockIdx.y * FAQ;
    const int tid  = threadIdx.x;
    const int wid  = tid >> 5;
    const int lane = tid & 31;
    const int g    = lane >> 2;
    const int t    = lane & 3;
    const int wm   = wid * 16;

    const float* qbase = QKV + ((size_t)(b * SEQ + q0)) * DQKV + h * DK;
    const float* kbase = QKV + ((size_t)(b * SEQ)) * DQKV + DM + h * DK;
    const float* vbase = QKV + ((size_t)(b * SEQ)) * DQKV + 2 * DM + h * DK;

    // ---- load Q tile (already tf32) into Ps area ----
    #pragma unroll
    for (int i = 0; i < 8; ++i) {
        const int f  = tid + i * 256;        // 0..2047
        const int r  = f >> 4;               // 0..127
        const int c4 = (f & 15) * 4;
        *(float4*)&Ps[r * QSTR + c4] = *(const float4*)(qbase + (size_t)r * DQKV + c4);
    }
    __syncthreads();

    // ---- extract Q fragments (kept in regs for whole kernel) ----
    uint32_t qf[8][4];
    #pragma unroll
    for (int ks = 0; ks < 8; ++ks) {
        const int kb = ks * 8;
        qf[ks][0] = __float_as_uint(Ps[(wm + g)     * QSTR + kb + t]);
        qf[ks][1] = __float_as_uint(Ps[(wm + g + 8) * QSTR + kb + t]);
        qf[ks][2] = __float_as_uint(Ps[(wm + g)     * QSTR + kb + t + 4]);
        qf[ks][3] = __float_as_uint(Ps[(wm + g + 8) * QSTR + kb + t + 4]);
    }
    __syncthreads();   // Ps now reusable as P tile

    float oc[8][4];
    #pragma unroll
    for (int i = 0; i < 8; i++)
        #pragma unroll
        for (int j = 0; j < 4; j++) oc[i][j] = 0.f;
    float m_g = -1e30f, m_g8 = -1e30f, l_g = 0.f, l_g8 = 0.f;

    const uint32_t ks_base = smem_u32(Ks);
    const uint32_t vs_base = smem_u32(Vs);
    const uint32_t ms_base = smem_u32(ms);

    auto issue_chunk = [&](int st, int kc) {
        const uint32_t ko = ks_base + (uint32_t)st * FA_KS_F * 4;
        const uint32_t vo = vs_base + (uint32_t)st * FA_VS_F * 4;
        #pragma unroll
        for (int i = 0; i < 4; ++i) {
            const int f  = tid + i * 256;    // 0..1023
            const int r  = f >> 4;           // 0..63
            const int c4 = (f & 15) * 4;
            const size_t gofs = (size_t)(kc * FAC + r) * DQKV + c4;
            cp_async16(ko + (r * KSTR + c4) * 4, kbase + gofs);
            cp_async16(vo + (r * VSTR + c4) * 4, vbase + gofs);
        }
        if (tid < 16)
            cp_async16(ms_base + st * FAC * 4 + tid * 16,
                       mask + b * SEQ + kc * FAC + tid * 4);
    };

    issue_chunk(0, 0);
    cp_commit();

    const int NC = SEQ / FAC;   // 32
    for (int kc = 0; kc < NC; ++kc) {
        const int st = kc & 1;
        cp_wait<0>();
        __syncthreads();
        if (kc + 1 < NC) issue_chunk(st ^ 1, kc + 1);
        cp_commit();

        const float* Kc = Ks + st * FA_KS_F;
        const float* Vc = Vs + st * FA_VS_F;
        const int*   mc = ms + st * FAC;

        // ---- S = Q @ K^T  (16 x 64 per warp) ----
        float sc[8][4];
        #pragma unroll
        for (int i = 0; i < 8; i++)
            #pragma unroll
            for (int j = 0; j < 4; j++) sc[i][j] = 0.f;

        #pragma unroll
        for (int ks = 0; ks < 8; ++ks) {
            const int kb = ks * 8;
            #pragma unroll
            for (int nt = 0; nt < 8; ++nt) {
                const uint32_t b0 = __float_as_uint(Kc[(nt * 8 + g) * KSTR + kb + t]);
                const uint32_t b1 = __float_as_uint(Kc[(nt * 8 + g) * KSTR + kb + t + 4]);
                mma_tf32(sc[nt][0], sc[nt][1], sc[nt][2], sc[nt][3],
                         qf[ks][0], qf[ks][1], qf[ks][2], qf[ks][3], b0, b1);
            }
        }

        // ---- scale + mask ----
        #pragma unroll
        for (int nt = 0; nt < 8; ++nt) {
            const int c0 = nt * 8 + 2 * t;
            const int m0 = mc[c0], m1 = mc[c0 + 1];
            sc[nt][0] = m0 ? sc[nt][0] * 0.125f : -1e9f;
            sc[nt][1] = m1 ? sc[nt][1] * 0.125f : -1e9f;
            sc[nt][2] = m0 ? sc[nt][2] * 0.125f : -1e9f;
            sc[nt][3] = m1 ? sc[nt][3] * 0.125f : -1e9f;
        }

        // ---- online softmax (rows g and g+8) ----
        float tg = -1e30f, tg8 = -1e30f;
        #pragma unroll
        for (int nt = 0; nt < 8; ++nt) {
            tg  = fmaxf(tg,  fmaxf(sc[nt][0], sc[nt][1]));
            tg8 = fmaxf(tg8, fmaxf(sc[nt][2], sc[nt][3]));
        }
        tg  = fmaxf(tg,  __shfl_xor_sync(0xFFFFFFFFu, tg,  1));
        tg  = fmaxf(tg,  __shfl_xor_sync(0xFFFFFFFFu, tg,  2));
        tg8 = fmaxf(tg8, __shfl_xor_sync(0xFFFFFFFFu, tg8, 1));
        tg8 = fmaxf(tg8, __shfl_xor_sync(0xFFFFFFFFu, tg8, 2));

        const float mn_g  = fmaxf(m_g,  tg);
        const float mn_g8 = fmaxf(m_g8, tg8);
        const float cg  = __expf(m_g  - mn_g);
        const float cg8 = __expf(m_g8 - mn_g8);
        m_g = mn_g; m_g8 = mn_g8;
        l_g *= cg; l_g8 *= cg8;
        #pragma unroll
        for (int nt = 0; nt < 8; ++nt) {
            oc[nt][0] *= cg;  oc[nt][1] *= cg;
            oc[nt][2] *= cg8; oc[nt][3] *= cg8;
        }

        // ---- P = exp(s-m), accumulate l, write to SMEM (tf32, warp-local) ----
        #pragma unroll
        for (int nt = 0; nt < 8; ++nt) {
            const float p0 = __expf(sc[nt][0] - m_g);
            const float p1 = __expf(sc[nt][1] - m_g);
            const float p2 = __expf(sc[nt][2] - m_g8);
            const float p3 = __expf(sc[nt][3] - m_g8);
            l_g  += p0 + p1;
            l_g8 += p2 + p3;
            float2 w0; w0.x = to_tf32(p0); w0.y = to_tf32(p1);
            float2 w1; w1.x = to_tf32(p2); w1.y = to_tf32(p3);
            *(float2*)&Ps[(wm + g)     * QSTR + nt * 8 + 2 * t] = w0;
            *(float2*)&Ps[(wm + g + 8) * QSTR + nt * 8 + 2 * t] = w1;
        }
        __syncwarp();

        // ---- O += P @ V  (V^T as col-major B: strided conflict-free reads) ----
        #pragma unroll
        for (int ks = 0; ks < 8; ++ks) {
            const int kb = ks * 8;
            const uint32_t a0 = __float_as_uint(Ps[(wm + g)     * QSTR + kb + t]);
            const uint32_t a1 = __float_as_uint(Ps[(wm + g + 8) * QSTR + kb + t]);
            const uint32_t a2 = __float_as_uint(Ps[(wm + g)     * QSTR + kb + t + 4]);
            const uint32_t a3 = __float_as_uint(Ps[(wm + g + 8) * QSTR + kb + t + 4]);
            #pragma unroll
            for (int nt = 0; nt < 8; ++nt) {
                const uint32_t b0 = __float_as_uint(Vc[(kb + t)     * VSTR + nt * 8 + g]);
                const uint32_t b1 = __float_as_uint(Vc[(kb + t + 4) * VSTR + nt * 8 + g]);
                mma_tf32(oc[nt][0], oc[nt][1], oc[nt][2], oc[nt][3],
                         a0, a1, a2, a3, b0, b1);
            }
        }
        __syncwarp();   // Ps rows are warp-local; full sync happens at loop top
    }

    // ---- finalize: reduce l across quad, normalize, write (tf32-rounded) ----
    l_g  += __shfl_xor_sync(0xFFFFFFFFu, l_g,  1);
    l_g  += __shfl_xor_sync(0xFFFFFFFFu, l_g,  2);
    l_g8 += __shfl_xor_sync(0xFFFFFFFFu, l_g8, 1);
    l_g8 += __shfl_xor_sync(0xFFFFFFFFu, l_g8, 2);
    const float ig  = 1.0f / l_g;
    const float ig8 = 1.0f / l_g8;

    const size_t row_g  = (size_t)(b * SEQ + q0 + wm + g);
    const size_t row_g8 = row_g + 8;
    #pragma unroll
    for (int nt = 0; nt < 8; ++nt) {
        const int col = h * DK + nt * 8 + 2 * t;
        float2 o0; o0.x = to_tf32(oc[nt][0] * ig);  o0.y = to_tf32(oc[nt][1] * ig);
        float2 o1; o1.x = to_tf32(oc[nt][2] * ig8); o1.y = to_tf32(oc[nt][3] * ig8);
        *(float2*)&O[row_g  * DM + col] = o0;
        *(float2*)&O[row_g8 * DM + col] = o1;
    }
}

// ---------------------------------------------------------------------------
// kernel_launch
// ---------------------------------------------------------------------------
extern "C" void kernel_launch(void* const* d_in, const int* in_sizes, int n_in,
                              void* d_out, int out_size)
{
    (void)in_sizes; (void)n_in; (void)out_size;
    const float* x     = (const float*)d_in[0];
    const int*   mask  = (const int*)  d_in[1];
    const float* Wq    = (const float*)d_in[2];
    const float* bq    = (const float*)d_in[3];
    const float* Wk    = (const float*)d_in[4];
    const float* bk    = (const float*)d_in[5];
    const float* Wv    = (const float*)d_in[6];
    const float* bv    = (const float*)d_in[7];
    const float* Wo    = (const float*)d_in[8];
    const float* bo    = (const float*)d_in[9];
    const float* W1    = (const float*)d_in[10];
    const float* b1    = (const float*)d_in[11];
    const float* W2    = (const float*)d_in[12];
    const float* b2    = (const float*)d_in[13];
    const float* ln1_g = (const float*)d_in[14];
    const float* ln1_b = (const float*)d_in[15];
    const float* ln2_g = (const float*)d_in[16];
    const float* ln2_b = (const float*)d_in[17];
    float* out = (float*)d_out;

    float *h, *qkv, *attn, *x2, *ff;
    float *wqkvT, *woT, *w1T, *w2T, *bqkv;
    cudaGetSymbolAddress((void**)&h,     g_h);
    cudaGetSymbolAddress((void**)&qkv,   g_qkv);
    cudaGetSymbolAddress((void**)&attn,  g_attn);
    cudaGetSymbolAddress((void**)&x2,    g_x2);
    cudaGetSymbolAddress((void**)&ff,    g_ff);
    cudaGetSymbolAddress((void**)&wqkvT, g_wqkvT);
    cudaGetSymbolAddress((void**)&woT,   g_woT);
    cudaGetSymbolAddress((void**)&w1T,   g_w1T);
    cudaGetSymbolAddress((void**)&w2T,   g_w2T);
    cudaGetSymbolAddress((void**)&bqkv,  g_bqkv);

    cudaFuncSetAttribute(mma_gemm<EPI_BIAS>,  cudaFuncAttributeMaxDynamicSharedMemorySize, GSMEM);
    cudaFuncSetAttribute(mma_gemm<EPI_RESID>, cudaFuncAttributeMaxDynamicSharedMemorySize, GSMEM);
    cudaFuncSetAttribute(mma_gemm<EPI_GELU>,  cudaFuncAttributeMaxDynamicSharedMemorySize, GSMEM);
    cudaFuncSetAttribute(flash_mma_kernel,    cudaFuncAttributeMaxDynamicSharedMemorySize, FA_SMEM);

    const dim3 tb(32, 8);
    const dim3 gQKV(DQKV / 128, NTOK / 128);   // (24, 64)
    const dim3 gD  (DM   / 128, NTOK / 128);   // (8, 64)
    const dim3 gFF (DFF  / 128, NTOK / 128);   // (32, 64)

    // Launch order chosen so launch index 5 (ncu -s 5 -c 1) = QKV GEMM.
    // 0-2: qkv weight transposes
    transpose_tf32<<<dim3(DM / 32, DM / 32), tb>>>(Wq, wqkvT,                       DM, DM);
    transpose_tf32<<<dim3(DM / 32, DM / 32), tb>>>(Wk, wqkvT + (size_t)DM * DM,     DM, DM);
    transpose_tf32<<<dim3(DM / 32, DM / 32), tb>>>(Wv, wqkvT + (size_t)2 * DM * DM, DM, DM);
    // 3: fused bias
    concat_bias<<<(DQKV + 255) / 256, 256>>>(bq, bk, bv, bqkv);
    // 4: h = LN1(x)
    ln_kernel<<<NTOK, 256>>>(x, ln1_g, ln1_b, h);
    // 5: fused QKV projection  (profiled next round)
    mma_gemm<EPI_BIAS><<<gQKV, 256, GSMEM>>>(h, wqkvT, bqkv, nullptr, qkv, NTOK, DQKV, DM);
    // 6: tensor-core flash attention
    flash_mma_kernel<<<dim3(BSZ * NH, SEQ / FAQ), 256, FA_SMEM>>>(qkv, mask, attn);
    // 7: Wo transpose; 8: x2 = x + attn @ Wo + bo
    transpose_tf32<<<dim3(DM / 32, DM / 32), tb>>>(Wo, woT, DM, DM);
    mma_gemm<EPI_RESID><<<gD, 256, GSMEM>>>(attn, woT, bo, x, x2, NTOK, DM, DM);
    // 9: h = LN2(x2)
    ln_kernel<<<NTOK, 256>>>(x2, ln2_g, ln2_b, h);
    // 10: W1 transpose; 11: ff = gelu(h @ W1 + b1)
    transpose_tf32<<<dim3(DFF / 32, DM / 32), tb>>>(W1, w1T, DM, DFF);
    mma_gemm<EPI_GELU><<<gFF, 256, GSMEM>>>(h, w1T, b1, nullptr, ff, NTOK, DFF, DM);
    // 12: W2 transpose; 13: out = x2 + ff @ W2 + b2
    transpose_tf32<<<dim3(DM / 32, DFF / 32), tb>>>(W2, w2T, DFF, DM);
    mma_gemm<EPI_RESID><<<gD, 256, GSMEM>>>(ff, w2T, b2, x2, out, NTOK, DM, DFF);
}

// round 16
// speedup vs baseline: 3.6444x; 1.0805x over previous
#include <cuda_runtime.h>
#include <cuda_bf16.h>
#include <cstddef>
#include <cstdint>

// ---------------------------------------------------------------------------
// Problem constants
// ---------------------------------------------------------------------------
#define BSZ   4
#define SEQ   2048
#define DM    1024
#define NH    16
#define DK    64
#define DFF   4096
#define NTOK  (BSZ*SEQ)            // 8192
#define DQKV  (3*DM)               // 3072

// ---------------------------------------------------------------------------
// Scratch (device globals)
// ---------------------------------------------------------------------------
__device__ float g_h   [(size_t)NTOK*DM];     // ln output (tf32, K-permuted)
__device__ float g_qkv [(size_t)NTOK*DQKV];   // fused qkv (tf32, linear)
__device__ float g_attn[(size_t)NTOK*DM];     // flash output (tf32, K-permuted)
__device__ float g_x2  [(size_t)NTOK*DM];     // linear fp32
__device__ float g_ff  [(size_t)NTOK*DFF];    // gelu output (tf32, K-permuted)
// transposed (tf32-rounded, K-permuted) weights: WT[n][perm(k)]
__device__ float g_wqkvT[(size_t)DM*DQKV];
__device__ float g_woT  [(size_t)DM*DM];
__device__ float g_w1T  [(size_t)DM*DFF];
__device__ float g_w2T  [(size_t)DFF*DM];
__device__ float g_bqkv [DQKV];

// ---------------------------------------------------------------------------
// Helpers
// ---------------------------------------------------------------------------
__device__ __forceinline__ float to_tf32(float x) {
    float r;
    asm("cvt.rna.tf32.f32 %0, %1;" : "=f"(r) : "f"(x));
    return r;
}
__device__ __forceinline__ float gelu_exact(float v) {
    return 0.5f * v * (1.0f + erff(v * 0.70710678118654752440f));
}
// K-permutation within each 16-float group: k -> (k%4)*4 + k/4
__device__ __forceinline__ int permk(int k) {
    return (k & ~15) | ((k & 3) << 2) | ((k & 15) >> 2);
}
__device__ __forceinline__ uint32_t smem_u32(const void* p) {
    uint32_t a;
    asm("{ .reg .u64 t; cvta.to.shared.u64 t, %1; cvt.u32.u64 %0, t; }"
        : "=r"(a) : "l"(p));
    return a;
}
__device__ __forceinline__ void cp_async16(uint32_t dst, const void* src) {
    asm volatile("cp.async.cg.shared.global [%0], [%1], 16;"
                 :: "r"(dst), "l"(src) : "memory");
}
__device__ __forceinline__ void cp_commit() {
    asm volatile("cp.async.commit_group;" ::: "memory");
}
template<int N>
__device__ __forceinline__ void cp_wait() {
    asm volatile("cp.async.wait_group %0;" :: "n"(N) : "memory");
}
__device__ __forceinline__ void mma_tf32(float& c0, float& c1, float& c2, float& c3,
                                         uint32_t a0, uint32_t a1, uint32_t a2, uint32_t a3,
                                         uint32_t b0, uint32_t b1) {
    asm volatile(
        "mma.sync.aligned.m16n8k8.row.col.f32.tf32.tf32.f32 "
        "{%0,%1,%2,%3}, {%4,%5,%6,%7}, {%8,%9}, {%0,%1,%2,%3};"
        : "+f"(c0), "+f"(c1), "+f"(c2), "+f"(c3)
        : "r"(a0), "r"(a1), "r"(a2), "r"(a3), "r"(b0), "r"(b1));
}

// ---------------------------------------------------------------------------
// Weight transpose with tf32 rounding + K-permute: W[K][N] -> WT[N][perm(K)]
// ---------------------------------------------------------------------------
__global__ __launch_bounds__(256)
void transpose_tf32(const float* __restrict__ W, float* __restrict__ WT, int K, int N)
{
    __shared__ float t[32][33];
    const int tx = threadIdx.x, ty = threadIdx.y;
    const int n0 = blockIdx.x * 32, k0 = blockIdx.y * 32;
    #pragma unroll
    for (int j = ty; j < 32; j += 8)
        t[j][tx] = to_tf32(W[(size_t)(k0 + j) * N + n0 + tx]);
    __syncthreads();
    const int pk = permk(tx);
    #pragma unroll
    for (int j = ty; j < 32; j += 8)
        WT[(size_t)(n0 + j) * K + k0 + pk] = t[tx][j];
}

__global__ __launch_bounds__(256)
void concat_bias(const float* __restrict__ bq, const float* __restrict__ bk,
                 const float* __restrict__ bv, float* __restrict__ o)
{
    const int i = blockIdx.x * 256 + threadIdx.x;
    if (i < DM)            o[i] = bq[i];
    else if (i < 2 * DM)   o[i] = bk[i - DM];
    else if (i < 3 * DM)   o[i] = bv[i - 2 * DM];
}

// ---------------------------------------------------------------------------
// LayerNorm: output tf32-rounded, K-permuted (feeds GEMM A operands only)
// ---------------------------------------------------------------------------
__global__ __launch_bounds__(256)
void ln_kernel(const float* __restrict__ x, const float* __restrict__ g,
               const float* __restrict__ b, float* __restrict__ y)
{
    const int t = blockIdx.x;
    const int i = threadIdx.x;
    const float* xp = x + (size_t)t * DM;

    float4 v = *(const float4*)(xp + i * 4);
    float s  = (v.x + v.y) + (v.z + v.w);
    float ss = fmaf(v.x, v.x, fmaf(v.y, v.y, fmaf(v.z, v.z, v.w * v.w)));

    #pragma unroll
    for (int o = 16; o > 0; o >>= 1) {
        s  += __shfl_xor_sync(0xFFFFFFFFu, s,  o);
        ss += __shfl_xor_sync(0xFFFFFFFFu, ss, o);
    }
    __shared__ float sh[16];
    const int w = i >> 5;
    if ((i & 31) == 0) { sh[w] = s; sh[8 + w] = ss; }
    __syncthreads();
    float S = 0.f, SS = 0.f;
    #pragma unroll
    for (int k = 0; k < 8; k++) { S += sh[k]; SS += sh[8 + k]; }

    const float mean = S * (1.0f / DM);
    const float var  = SS * (1.0f / DM) - mean * mean;
    const float r    = rsqrtf(var + 1e-5f);

    float4 gg = *(const float4*)(g + i * 4);
    float4 bb = *(const float4*)(b + i * 4);
    // k = 4i + c  ->  perm dest: blk=(i>>2)*16, off = c*4 + (i&3)
    float* yp = y + (size_t)t * DM + (i >> 2) * 16 + (i & 3);
    yp[0]  = to_tf32((v.x - mean) * r * gg.x + bb.x);
    yp[4]  = to_tf32((v.y - mean) * r * gg.y + bb.y);
    yp[8]  = to_tf32((v.z - mean) * r * gg.z + bb.z);
    yp[12] = to_tf32((v.w - mean) * r * gg.w + bb.w);
}

// ---------------------------------------------------------------------------
// TF32 mma.sync GEMM, cp.async 3-stage pipeline, K-permuted operands,
// LDS.128 fragment loads. C[M,N] = A[M,K] @ BT[N,K]^T + bias (+epilogue).
// TN = CTA tile N (128 or 256); CTA tile M = 128; warp tile 64 x TN/4.
// ---------------------------------------------------------------------------
#define EPI_BIAS  0   // + bias, tf32-round, LINEAR store (feeds flash)
#define EPI_RESID 1   // + bias + residual, fp32 LINEAR store
#define EPI_GELU  2   // + bias, gelu, tf32-round, PERMUTED store (feeds FFN2)

#define MBK     16
#define STAGES  3

template<int EPI, int TN>
__global__ __launch_bounds__(256)
void mma_gemm(const float* __restrict__ A, const float* __restrict__ BT,
              const float* __restrict__ bias, const float* __restrict__ res,
              float* __restrict__ C, int M, int N, int K)
{
    constexpr int WN  = TN / 4;            // warp tile N
    constexpr int NT  = WN / 8;            // B n-tiles per warp
    constexpr int SS  = (128 + TN) * MBK;  // floats per stage (A then B)
    constexpr int NCP = (128 + TN) * 4;    // cp.async16 per stage

    extern __shared__ __align__(16) float sm[];

    const int tid  = threadIdx.x;
    const int wid  = tid >> 5;
    const int lane = tid & 31;
    const int g    = lane >> 2;
    const int t    = lane & 3;

    const int warp_m = (wid & 1) * 64;
    const int warp_n = (wid >> 1) * WN;
    const int row0 = blockIdx.y * 128;
    const int col0 = blockIdx.x * TN;

    const uint32_t sm_base = smem_u32(sm);

    auto issue_load = [&](int stage, int kk) {
        const uint32_t so = sm_base + (uint32_t)stage * SS * 4;
        #pragma unroll
        for (int i = 0; i < NCP / 256; ++i) {
            const int f = tid + i * 256;
            const int r = f >> 2;
            const int c = (f & 3) * 4;
            const float* src = (r < 128)
                ? A  + (size_t)(row0 + r) * K + kk + c
                : BT + (size_t)(col0 + r - 128) * K + kk + c;
            cp_async16(so + (r * MBK + c) * 4, src);
        }
    };

    float acc[4][NT][4];
    #pragma unroll
    for (int i = 0; i < 4; i++)
        #pragma unroll
        for (int j = 0; j < NT; j++)
            #pragma unroll
            for (int q = 0; q < 4; q++) acc[i][j][q] = 0.f;

    const int nc = K / MBK;

    #pragma unroll
    for (int s = 0; s < STAGES - 1; ++s) {
        if (s < nc) issue_load(s, s * MBK);
        cp_commit();
    }

    for (int ch = 0; ch < nc; ++ch) {
        cp_wait<STAGES - 2>();
        __syncthreads();

        if (ch + STAGES - 1 < nc) issue_load((ch + STAGES - 1) % STAGES, (ch + STAGES - 1) * MBK);
        cp_commit();

        const float* Ab = sm + (ch % STAGES) * SS;
        const float* Bb = Ab + 128 * MBK;

        // fragment loads: one LDS.128 per row covers BOTH k-steps
        float4 af[4][2];
        #pragma unroll
        for (int mt = 0; mt < 4; ++mt) {
            const int m = warp_m + mt * 16;
            af[mt][0] = *(const float4*)&Ab[(m + g)     * MBK + 4 * t];
            af[mt][1] = *(const float4*)&Ab[(m + g + 8) * MBK + 4 * t];
        }
        float4 bf[NT];
        #pragma unroll
        for (int nt = 0; nt < NT; ++nt)
            bf[nt] = *(const float4*)&Bb[(warp_n + nt * 8 + g) * MBK + 4 * t];

        #pragma unroll
        for (int mt = 0; mt < 4; ++mt) {
            const uint32_t a00 = __float_as_uint(af[mt][0].x);
            const uint32_t a01 = __float_as_uint(af[mt][1].x);
            const uint32_t a02 = __float_as_uint(af[mt][0].y);
            const uint32_t a03 = __float_as_uint(af[mt][1].y);
            const uint32_t a10 = __float_as_uint(af[mt][0].z);
            const uint32_t a11 = __float_as_uint(af[mt][1].z);
            const uint32_t a12 = __float_as_uint(af[mt][0].w);
            const uint32_t a13 = __float_as_uint(af[mt][1].w);
            #pragma unroll
            for (int nt = 0; nt < NT; ++nt) {
                mma_tf32(acc[mt][nt][0], acc[mt][nt][1], acc[mt][nt][2], acc[mt][nt][3],
                         a00, a01, a02, a03,
                         __float_as_uint(bf[nt].x), __float_as_uint(bf[nt].y));
                mma_tf32(acc[mt][nt][0], acc[mt][nt][1], acc[mt][nt][2], acc[mt][nt][3],
                         a10, a11, a12, a13,
                         __float_as_uint(bf[nt].z), __float_as_uint(bf[nt].w));
            }
        }
        __syncthreads();
    }

    // ---- epilogue ----
    #pragma unroll
    for (int mt = 0; mt < 4; ++mt) {
        const int mb = row0 + warp_m + mt * 16;
        #pragma unroll
        for (int nt = 0; nt < NT; ++nt) {
            const int nb = col0 + warp_n + nt * 8 + 2 * t;
            const float b0 = bias[nb], b1 = bias[nb + 1];
            #pragma unroll
            for (int half = 0; half < 2; ++half) {
                const int r = mb + g + half * 8;
                float vx = acc[mt][nt][2 * half + 0] + b0;
                float vy = acc[mt][nt][2 * half + 1] + b1;
                if (EPI == EPI_BIAS) {           // linear tf32 (flash reads)
                    float2 o; o.x = to_tf32(vx); o.y = to_tf32(vy);
                    *(float2*)(C + (size_t)r * N + nb) = o;
                }
                if (EPI == EPI_GELU) {           // permuted tf32 (FFN2 A)
                    C[(size_t)r * N + permk(nb)]     = to_tf32(gelu_exact(vx));
                    C[(size_t)r * N + permk(nb + 1)] = to_tf32(gelu_exact(vy));
                }
                if (EPI == EPI_RESID) {          // linear fp32 + residual
                    const float2 rr = *(const float2*)(res + (size_t)r * N + nb);
                    float2 o; o.x = vx + rr.x; o.y = vy + rr.y;
                    *(float2*)(C + (size_t)r * N + nb) = o;
                }
            }
        }
    }
}

#define SMEM_G(TN) (STAGES * (128 + (TN)) * MBK * 4)

// ---------------------------------------------------------------------------
// Tensor-core flash attention (tf32 mma.sync) — unchanged from R13 except
// the epilogue stores K-permuted (attn feeds the Wo GEMM A operand).
// ---------------------------------------------------------------------------
#define FAQ   128
#define FAC   64
#define QSTR  68
#define KSTR  68
#define VSTR  72
#define FA_PS_F   (FAQ * QSTR)
#define FA_KS_F   (FAC * KSTR)
#define FA_VS_F   (FAC * VSTR)
#define FA_SMEM   ((FA_PS_F + 2*FA_KS_F + 2*FA_VS_F) * 4 + 2*FAC*4)

__global__ __launch_bounds__(256)
void flash_mma_kernel(const float* __restrict__ QKV, const int* __restrict__ mask,
                      float* __restrict__ O)
{
    extern __shared__ __align__(16) float fsm[];
    float* Ps = fsm;
    float* Ks = fsm + FA_PS_F;
    float* Vs = Ks + 2 * FA_KS_F;
    int*   ms = (int*)(Vs + 2 * FA_VS_F);

    const int bh = blockIdx.x;
    const int b  = bh >> 4;
    const int h  = bh & 15;
    const int q0 = blockIdx.y * FAQ;
    const int tid  = threadIdx.x;
    const int wid  = tid >> 5;
    const int lane = tid & 31;
    const int g    = lane >> 2;
    const int t    = lane & 3;
    const int wm   = wid * 16;

    const float* qbase = QKV + ((size_t)(b * SEQ + q0)) * DQKV + h * DK;
    const float* kbase = QKV + ((size_t)(b * SEQ)) * DQKV + DM + h * DK;
    const float* vbase = QKV + ((size_t)(b * SEQ)) * DQKV + 2 * DM + h * DK;

    #pragma unroll
    for (int i = 0; i < 8; ++i) {
        const int f  = tid + i * 256;
        const int r  = f >> 4;
        const int c4 = (f & 15) * 4;
        *(float4*)&Ps[r * QSTR + c4] = *(const float4*)(qbase + (size_t)r * DQKV + c4);
    }
    __syncthreads();

    uint32_t qf[8][4];
    #pragma unroll
    for (int ks = 0; ks < 8; ++ks) {
        const int kb = ks * 8;
        qf[ks][0] = __float_as_uint(Ps[(wm + g)     * QSTR + kb + t]);
        qf[ks][1] = __float_as_uint(Ps[(wm + g + 8) * QSTR + kb + t]);
        qf[ks][2] = __float_as_uint(Ps[(wm + g)     * QSTR + kb + t + 4]);
        qf[ks][3] = __float_as_uint(Ps[(wm + g + 8) * QSTR + kb + t + 4]);
    }
    __syncthreads();

    float oc[8][4];
    #pragma unroll
    for (int i = 0; i < 8; i++)
        #pragma unroll
        for (int j = 0; j < 4; j++) oc[i][j] = 0.f;
    float m_g = -1e30f, m_g8 = -1e30f, l_g = 0.f, l_g8 = 0.f;

    const uint32_t ks_base = smem_u32(Ks);
    const uint32_t vs_base = smem_u32(Vs);
    const uint32_t ms_base = smem_u32(ms);

    auto issue_chunk = [&](int st, int kc) {
        const uint32_t ko = ks_base + (uint32_t)st * FA_KS_F * 4;
        const uint32_t vo = vs_base + (uint32_t)st * FA_VS_F * 4;
        #pragma unroll
        for (int i = 0; i < 4; ++i) {
            const int f  = tid + i * 256;
            const int r  = f >> 4;
            const int c4 = (f & 15) * 4;
            const size_t gofs = (size_t)(kc * FAC + r) * DQKV + c4;
            cp_async16(ko + (r * KSTR + c4) * 4, kbase + gofs);
            cp_async16(vo + (r * VSTR + c4) * 4, vbase + gofs);
        }
        if (tid < 16)
            cp_async16(ms_base + st * FAC * 4 + tid * 16,
                       mask + b * SEQ + kc * FAC + tid * 4);
    };

    issue_chunk(0, 0);
    cp_commit();

    const int NC = SEQ / FAC;
    for (int kc = 0; kc < NC; ++kc) {
        const int st = kc & 1;
        cp_wait<0>();
        __syncthreads();
        if (kc + 1 < NC) issue_chunk(st ^ 1, kc + 1);
        cp_commit();

        const float* Kc = Ks + st * FA_KS_F;
        const float* Vc = Vs + st * FA_VS_F;
        const int*   mc = ms + st * FAC;

        float sc[8][4];
        #pragma unroll
        for (int i = 0; i < 8; i++)
            #pragma unroll
            for (int j = 0; j < 4; j++) sc[i][j] = 0.f;

        #pragma unroll
        for (int ks = 0; ks < 8; ++ks) {
            const int kb = ks * 8;
            #pragma unroll
            for (int nt = 0; nt < 8; ++nt) {
                const uint32_t b0 = __float_as_uint(Kc[(nt * 8 + g) * KSTR + kb + t]);
                const uint32_t b1 = __float_as_uint(Kc[(nt * 8 + g) * KSTR + kb + t + 4]);
                mma_tf32(sc[nt][0], sc[nt][1], sc[nt][2], sc[nt][3],
                         qf[ks][0], qf[ks][1], qf[ks][2], qf[ks][3], b0, b1);
            }
        }

        #pragma unroll
        for (int nt = 0; nt < 8; ++nt) {
            const int c0 = nt * 8 + 2 * t;
            const int m0 = mc[c0], m1 = mc[c0 + 1];
            sc[nt][0] = m0 ? sc[nt][0] * 0.125f : -1e9f;
            sc[nt][1] = m1 ? sc[nt][1] * 0.125f : -1e9f;
            sc[nt][2] = m0 ? sc[nt][2] * 0.125f : -1e9f;
            sc[nt][3] = m1 ? sc[nt][3] * 0.125f : -1e9f;
        }

        float tg = -1e30f, tg8 = -1e30f;
        #pragma unroll
        for (int nt = 0; nt < 8; ++nt) {
            tg  = fmaxf(tg,  fmaxf(sc[nt][0], sc[nt][1]));
            tg8 = fmaxf(tg8, fmaxf(sc[nt][2], sc[nt][3]));
        }
        tg  = fmaxf(tg,  __shfl_xor_sync(0xFFFFFFFFu, tg,  1));
        tg  = fmaxf(tg,  __shfl_xor_sync(0xFFFFFFFFu, tg,  2));
        tg8 = fmaxf(tg8, __shfl_xor_sync(0xFFFFFFFFu, tg8, 1));
        tg8 = fmaxf(tg8, __shfl_xor_sync(0xFFFFFFFFu, tg8, 2));

        const float mn_g  = fmaxf(m_g,  tg);
        const float mn_g8 = fmaxf(m_g8, tg8);
        const float cg  = __expf(m_g  - mn_g);
        const float cg8 = __expf(m_g8 - mn_g8);
        m_g = mn_g; m_g8 = mn_g8;
        l_g *= cg; l_g8 *= cg8;
        #pragma unroll
        for (int nt = 0; nt < 8; ++nt) {
            oc[nt][0] *= cg;  oc[nt][1] *= cg;
            oc[nt][2] *= cg8; oc[nt][3] *= cg8;
        }

        #pragma unroll
        for (int nt = 0; nt < 8; ++nt) {
            const float p0 = __expf(sc[nt][0] - m_g);
            const float p1 = __expf(sc[nt][1] - m_g);
            const float p2 = __expf(sc[nt][2] - m_g8);
            const float p3 = __expf(sc[nt][3] - m_g8);
            l_g  += p0 + p1;
            l_g8 += p2 + p3;
            float2 w0; w0.x = to_tf32(p0); w0.y = to_tf32(p1);
            float2 w1; w1.x = to_tf32(p2); w1.y = to_tf32(p3);
            *(float2*)&Ps[(wm + g)     * QSTR + nt * 8 + 2 * t] = w0;
            *(float2*)&Ps[(wm + g + 8) * QSTR + nt * 8 + 2 * t] = w1;
        }
        __syncwarp();

        #pragma unroll
        for (int ks = 0; ks < 8; ++ks) {
            const int kb = ks * 8;
            const uint32_t a0 = __float_as_uint(Ps[(wm + g)     * QSTR + kb + t]);
            const uint32_t a1 = __float_as_uint(Ps[(wm + g + 8) * QSTR + kb + t]);
            const uint32_t a2 = __float_as_uint(Ps[(wm + g)     * QSTR + kb + t + 4]);
            const uint32_t a3 = __float_as_uint(Ps[(wm + g + 8) * QSTR + kb + t + 4]);
            #pragma unroll
            for (int nt = 0; nt < 8; ++nt) {
                const uint32_t b0 = __float_as_uint(Vc[(kb + t)     * VSTR + nt * 8 + g]);
                const uint32_t b1 = __float_as_uint(Vc[(kb + t + 4) * VSTR + nt * 8 + g]);
                mma_tf32(oc[nt][0], oc[nt][1], oc[nt][2], oc[nt][3],
                         a0, a1, a2, a3, b0, b1);
            }
        }
        __syncwarp();
    }

    l_g  += __shfl_xor_sync(0xFFFFFFFFu, l_g,  1);
    l_g  += __shfl_xor_sync(0xFFFFFFFFu, l_g,  2);
    l_g8 += __shfl_xor_sync(0xFFFFFFFFu, l_g8, 1);
    l_g8 += __shfl_xor_sync(0xFFFFFFFFu, l_g8, 2);
    const float ig  = 1.0f / l_g;
    const float ig8 = 1.0f / l_g8;

    const size_t row_g  = (size_t)(b * SEQ + q0 + wm + g);
    const size_t row_g8 = row_g + 8;
    #pragma unroll
    for (int nt = 0; nt < 8; ++nt) {
        const int col = h * DK + nt * 8 + 2 * t;
        // K-permuted stores: attn feeds the Wo GEMM A operand
        O[row_g  * DM + permk(col)]     = to_tf32(oc[nt][0] * ig);
        O[row_g  * DM + permk(col + 1)] = to_tf32(oc[nt][1] * ig);
        O[row_g8 * DM + permk(col)]     = to_tf32(oc[nt][2] * ig8);
        O[row_g8 * DM + permk(col + 1)] = to_tf32(oc[nt][3] * ig8);
    }
}

// ---------------------------------------------------------------------------
// kernel_launch
// ---------------------------------------------------------------------------
extern "C" void kernel_launch(void* const* d_in, const int* in_sizes, int n_in,
                              void* d_out, int out_size)
{
    (void)in_sizes; (void)n_in; (void)out_size;
    const float* x     = (const float*)d_in[0];
    const int*   mask  = (const int*)  d_in[1];
    const float* Wq    = (const float*)d_in[2];
    const float* bq    = (const float*)d_in[3];
    const float* Wk    = (const float*)d_in[4];
    const float* bk    = (const float*)d_in[5];
    const float* Wv    = (const float*)d_in[6];
    const float* bv    = (const float*)d_in[7];
    const float* Wo    = (const float*)d_in[8];
    const float* bo    = (const float*)d_in[9];
    const float* W1    = (const float*)d_in[10];
    const float* b1    = (const float*)d_in[11];
    const float* W2    = (const float*)d_in[12];
    const float* b2    = (const float*)d_in[13];
    const float* ln1_g = (const float*)d_in[14];
    const float* ln1_b = (const float*)d_in[15];
    const float* ln2_g = (const float*)d_in[16];
    const float* ln2_b = (const float*)d_in[17];
    float* out = (float*)d_out;

    float *h, *qkv, *attn, *x2, *ff;
    float *wqkvT, *woT, *w1T, *w2T, *bqkv;
    cudaGetSymbolAddress((void**)&h,     g_h);
    cudaGetSymbolAddress((void**)&qkv,   g_qkv);
    cudaGetSymbolAddress((void**)&attn,  g_attn);
    cudaGetSymbolAddress((void**)&x2,    g_x2);
    cudaGetSymbolAddress((void**)&ff,    g_ff);
    cudaGetSymbolAddress((void**)&wqkvT, g_wqkvT);
    cudaGetSymbolAddress((void**)&woT,   g_woT);
    cudaGetSymbolAddress((void**)&w1T,   g_w1T);
    cudaGetSymbolAddress((void**)&w2T,   g_w2T);
    cudaGetSymbolAddress((void**)&bqkv,  g_bqkv);

    cudaFuncSetAttribute((const void*)mma_gemm<EPI_BIAS, 256>,
                         cudaFuncAttributeMaxDynamicSharedMemorySize, SMEM_G(256));
    cudaFuncSetAttribute((const void*)mma_gemm<EPI_GELU, 256>,
                         cudaFuncAttributeMaxDynamicSharedMemorySize, SMEM_G(256));
    cudaFuncSetAttribute((const void*)mma_gemm<EPI_RESID, 128>,
                         cudaFuncAttributeMaxDynamicSharedMemorySize, SMEM_G(128));
    cudaFuncSetAttribute(flash_mma_kernel,
                         cudaFuncAttributeMaxDynamicSharedMemorySize, FA_SMEM);

    const dim3 tb(32, 8);
    // 0-2: qkv weight transposes (tf32 + K-permute)
    transpose_tf32<<<dim3(DM / 32, DM / 32), tb>>>(Wq, wqkvT,                       DM, DM);
    transpose_tf32<<<dim3(DM / 32, DM / 32), tb>>>(Wk, wqkvT + (size_t)DM * DM,     DM, DM);
    transpose_tf32<<<dim3(DM / 32, DM / 32), tb>>>(Wv, wqkvT + (size_t)2 * DM * DM, DM, DM);
    // 3: fused bias
    concat_bias<<<(DQKV + 255) / 256, 256>>>(bq, bk, bv, bqkv);
    // 4: h = LN1(x)  (tf32, permuted)
    ln_kernel<<<NTOK, 256>>>(x, ln1_g, ln1_b, h);
    // 5: fused QKV projection (128x256 tiles)
    mma_gemm<EPI_BIAS, 256><<<dim3(DQKV / 256, NTOK / 128), 256, SMEM_G(256)>>>
        (h, wqkvT, bqkv, nullptr, qkv, NTOK, DQKV, DM);
    // 6: tensor-core flash attention
    flash_mma_kernel<<<dim3(BSZ * NH, SEQ / FAQ), 256, FA_SMEM>>>(qkv, mask, attn);
    // 7-8: Wo transpose; x2 = x + attn @ Wo + bo   (128x128 tiles)
    transpose_tf32<<<dim3(DM / 32, DM / 32), tb>>>(Wo, woT, DM, DM);
    mma_gemm<EPI_RESID, 128><<<dim3(DM / 128, NTOK / 128), 256, SMEM_G(128)>>>
        (attn, woT, bo, x, x2, NTOK, DM, DM);
    // 9: h = LN2(x2)
    ln_kernel<<<NTOK, 256>>>(x2, ln2_g, ln2_b, h);
    // 10-11: W1 transpose; ff = gelu(h @ W1 + b1)   (128x256 tiles)
    transpose_tf32<<<dim3(DFF / 32, DM / 32), tb>>>(W1, w1T, DM, DFF);
    mma_gemm<EPI_GELU, 256><<<dim3(DFF / 256, NTOK / 128), 256, SMEM_G(256)>>>
        (h, w1T, b1, nullptr, ff, NTOK, DFF, DM);
    // 12-13: W2 transpose; out = x2 + ff @ W2 + b2  (128x128 tiles)
    transpose_tf32<<<dim3(DM / 32, DFF / 32), tb>>>(W2, w2T, DFF, DM);
    mma_gemm<EPI_RESID, 128><<<dim3(DM / 128, NTOK / 128), 256, SMEM_G(128)>>>
        (ff, w2T, b2, x2, out, NTOK, DM, DFF);
}